// round 3
// baseline (speedup 1.0000x reference)
#include <cuda_runtime.h>

// NeuralSurface SDF MLP, fully fused, fp32 with packed f32x2 FMA (Blackwell FFMA2).
// One CTA = 64 points. Activations live in SMEM for the whole 9-pass chain.

#define BLOCKT 256
#define TILE_M 64
#define XP 260            // activation pitch (floats), multiple of 4, conflict-free stores
#define EMBP 64           // embedding buffer pitch
#define KC 64             // K-chunk staged into SMEM per step

// SMEM layout (float offsets)
#define OFF_E 0                       // embS[64][64]
#define OFF_A (64 * 64)               // A[64][260]
#define OFF_B (OFF_A + 64 * XP)       // B[64][260]
#define OFF_W (OFF_B + 64 * XP)       // Ws[64][256]
#define SMEM_FLOATS (OFF_W + 64 * 256)

__device__ __forceinline__ void fma2(unsigned long long& c, unsigned long long a,
                                     unsigned long long b) {
    asm("fma.rn.f32x2 %0, %1, %2, %0;" : "+l"(c) : "l"(a), "l"(b));
}

__global__ __launch_bounds__(BLOCKT, 1)
void sdf_mlp_kernel(const float* __restrict__ pts,
                    const float* __restrict__ w0, const float* __restrict__ b0,
                    const float* __restrict__ w1, const float* __restrict__ b1,
                    const float* __restrict__ w2, const float* __restrict__ b2,
                    const float* __restrict__ w3, const float* __restrict__ b3,
                    const float* __restrict__ w4, const float* __restrict__ b4,
                    const float* __restrict__ w5, const float* __restrict__ b5,
                    const float* __restrict__ w6, const float* __restrict__ b6,
                    const float* __restrict__ w7, const float* __restrict__ b7,
                    const float* __restrict__ wsdf, const float* __restrict__ bsdf,
                    float* __restrict__ out) {
    extern __shared__ float smem[];
    const int tid = threadIdx.x;
    const int tm = tid >> 5;   // 0..7  -> rows tm*8 .. tm*8+7
    const int tn = tid & 31;   // 0..31 -> cols tn*8 .. tn*8+7
    const int tileBase = blockIdx.x * TILE_M;

    // ---- harmonic embedding: emb[k] = [sin(x_c * 2^h) (18), cos (18), xyz (3)], pad->64 ----
    if (tid < TILE_M) {
        const float* pp = pts + (size_t)(tileBase + tid) * 3;
        float co[3];
        co[0] = pp[0]; co[1] = pp[1]; co[2] = pp[2];
        float* er = smem + OFF_E + tid * EMBP;
        #pragma unroll
        for (int c = 0; c < 3; ++c) {
            float f = 1.0f;
            #pragma unroll
            for (int h = 0; h < 6; ++h) {
                float a = co[c] * f;
                float s, cs;
                sincosf(a, &s, &cs);
                er[c * 6 + h] = s;
                er[18 + c * 6 + h] = cs;
                f *= 2.0f;
            }
        }
        er[36] = co[0]; er[37] = co[1]; er[38] = co[2];
        #pragma unroll
        for (int k = 39; k < 64; ++k) er[k] = 0.0f;  // padded K with zero weights
    }

    // ---- pass table: 8 layers, layer 4 split into (emb-part, h-part) ----
    const float* wp[9]  = {w0, w1, w2, w3, w4, w4, w5, w6, w7};
    const float* bp[9]  = {b0, b1, b2, b3, 0,  b4, b5, b6, b7};
    const int wr0[9]    = {0, 0, 0, 0, 0, 39, 0, 0, 0};      // W row offset
    const int wrs[9]    = {39, 256, 256, 256, 39, 256, 256, 256, 256}; // valid W rows
    const int kpd[9]    = {64, 256, 256, 256, 64, 256, 256, 256, 256}; // padded K loop
    const int soff[9]   = {OFF_E, OFF_A, OFF_B, OFF_A, OFF_E, OFF_B, OFF_A, OFF_B, OFF_A};
    const int spit[9]   = {EMBP, XP, XP, XP, EMBP, XP, XP, XP, XP};
    const int doff[9]   = {OFF_A, OFF_B, OFF_A, OFF_B, 0, OFF_A, OFF_B, OFF_A, OFF_B};
    const int clr[9]    = {1, 1, 1, 1, 1, 0, 1, 1, 1};

    unsigned long long acc[8][4];  // 8 rows x 4 col-pairs (packed f32x2)
    float* Ws = smem + OFF_W;

    #pragma unroll 1
    for (int ps = 0; ps < 9; ++ps) {
        if (clr[ps]) {
            #pragma unroll
            for (int i = 0; i < 8; ++i)
                #pragma unroll
                for (int j = 0; j < 4; ++j) acc[i][j] = 0ull;
        }
        const float* Wg = wp[ps];
        const float* Xs = smem + soff[ps];
        const int xp = spit[ps];
        const int r0 = wr0[ps], rs = wrs[ps], kp = kpd[ps];

        #pragma unroll 1
        for (int kk0 = 0; kk0 < kp; kk0 += KC) {
            __syncthreads();  // previous Ws readers done / prior-pass stores visible
            // stage 64x256 weight chunk (rows beyond valid range -> 0)
            #pragma unroll
            for (int it = 0; it < 16; ++it) {
                int idx = tid + it * BLOCKT;
                int row = idx >> 6;
                int cg = idx & 63;
                int kl = kk0 + row;
                float4 v = make_float4(0.f, 0.f, 0.f, 0.f);
                if (kl < rs)
                    v = __ldg(reinterpret_cast<const float4*>(Wg + (r0 + kl) * 256 + cg * 4));
                *reinterpret_cast<float4*>(Ws + row * 256 + cg * 4) = v;
            }
            __syncthreads();

            const float* xrow = Xs + tm * 8 * xp + kk0;
            #pragma unroll 1
            for (int kk = 0; kk < KC; kk += 4) {
                float4 xv[8];
                #pragma unroll
                for (int i = 0; i < 8; ++i)
                    xv[i] = *reinterpret_cast<const float4*>(xrow + i * xp + kk);
                const float* wrow = Ws + kk * 256 + tn * 8;
                #pragma unroll
                for (int dk = 0; dk < 4; ++dk) {
                    ulonglong2 wA = *reinterpret_cast<const ulonglong2*>(wrow + dk * 256);
                    ulonglong2 wB = *reinterpret_cast<const ulonglong2*>(wrow + dk * 256 + 4);
                    #pragma unroll
                    for (int i = 0; i < 8; ++i) {
                        float xf = (dk == 0) ? xv[i].x : (dk == 1) ? xv[i].y
                                 : (dk == 2) ? xv[i].z : xv[i].w;
                        unsigned xu = __float_as_uint(xf);
                        unsigned long long xx;
                        asm("mov.b64 %0, {%1, %1};" : "=l"(xx) : "r"(xu));
                        fma2(acc[i][0], xx, wA.x);
                        fma2(acc[i][1], xx, wA.y);
                        fma2(acc[i][2], xx, wB.x);
                        fma2(acc[i][3], xx, wB.y);
                    }
                }
            }
        }

        // epilogue: bias + relu + store (skipped for the emb-part of layer 4)
        if (bp[ps]) {
            const float* bb = bp[ps];
            float bj[8];
            #pragma unroll
            for (int j = 0; j < 8; ++j) bj[j] = __ldg(bb + tn * 8 + j);
            float* dst = smem + doff[ps] + tm * 8 * XP + tn * 8;
            #pragma unroll
            for (int i = 0; i < 8; ++i) {
                float v[8];
                #pragma unroll
                for (int jp = 0; jp < 4; ++jp) {
                    unsigned lo, hi;
                    asm("mov.b64 {%0, %1}, %2;" : "=r"(lo), "=r"(hi) : "l"(acc[i][jp]));
                    v[2 * jp]     = fmaxf(__uint_as_float(lo) + bj[2 * jp], 0.f);
                    v[2 * jp + 1] = fmaxf(__uint_as_float(hi) + bj[2 * jp + 1], 0.f);
                }
                *reinterpret_cast<float4*>(dst + i * XP)     = make_float4(v[0], v[1], v[2], v[3]);
                *reinterpret_cast<float4*>(dst + i * XP + 4) = make_float4(v[4], v[5], v[6], v[7]);
            }
        }
    }

    __syncthreads();
    // ---- SDF head: out[p] = h7[p] . wsdf + bsdf ; 4 threads per point ----
    {
        int p = tid >> 2;
        int part = tid & 3;
        const float* xr = smem + OFF_B + p * XP + part * 64;
        const float* wv = wsdf + part * 64;
        float s = 0.f;
        #pragma unroll 8
        for (int k = 0; k < 64; ++k) s += xr[k] * __ldg(wv + k);
        s += __shfl_xor_sync(0xffffffffu, s, 1);
        s += __shfl_xor_sync(0xffffffffu, s, 2);
        if (part == 0) out[tileBase + p] = s + __ldg(bsdf);
    }
}

extern "C" void kernel_launch(void* const* d_in, const int* in_sizes, int n_in,
                              void* d_out, int out_size) {
    const float* pts = (const float*)d_in[0];
    const float* W[8];
    const float* B[8];
    for (int i = 0; i < 8; ++i) {
        W[i] = (const float*)d_in[1 + 2 * i];
        B[i] = (const float*)d_in[2 + 2 * i];
    }
    const float* wsdf = (const float*)d_in[17];
    const float* bsdf = (const float*)d_in[18];
    int n = in_sizes[0] / 3;           // 262144
    int grid = n / TILE_M;             // 4096 tiles
    size_t shmem = (size_t)SMEM_FLOATS * sizeof(float);  // 215040 B

    cudaFuncSetAttribute(sdf_mlp_kernel,
                         cudaFuncAttributeMaxDynamicSharedMemorySize, (int)shmem);
    sdf_mlp_kernel<<<grid, BLOCKT, shmem>>>(
        pts,
        W[0], B[0], W[1], B[1], W[2], B[2], W[3], B[3],
        W[4], B[4], W[5], B[5], W[6], B[6], W[7], B[7],
        wsdf, bsdf, (float*)d_out);
}

// round 5
// speedup vs baseline: 2.1847x; 2.1847x over previous
#include <cuda_runtime.h>
#include <cuda_bf16.h>
#include <stdint.h>

// ============================================================
// NeuralSurface SDF MLP via mma.sync bf16 (hi/lo split, fp32 acc).
// Base-target PTX only (no tcgen05 — harness PTX target is sm_103).
// 128 points/CTA, 8 warps (2Mx4N), warp tile 64x64, K chunks of 32
// double-buffered with cp.async from a pre-packed weight scratch.
// ============================================================

#define THREADS 256
#define TILE_M  128

// smem byte offsets
#define OFF_XH   0            // X hi: 128 rows x 512 B
#define OFF_XL   65536        // X lo
#define OFF_WB   131072       // two 32 KB weight chunk buffers
#define OFF_EMBH 196608       // emb hi: 128 x 128 B
#define OFF_EMBL 212992       // emb lo
#define OFF_RED  196608       // head reduction (reuses emb area)
#define OFF_WSDF 229376       // 256 floats
#define SMEM_BYTES 230400

#define CHUNK_BYTES 32768     // hi tiles (16 KB) + lo tiles (16 KB)
#define HALF_BYTES  16384
#define N_CHUNKS    60

__device__ __align__(128) unsigned char g_wt[(size_t)N_CHUNKS * CHUNK_BYTES];

// ---------------- helpers ----------------
static __device__ __forceinline__ uint32_t smem_u32(const void* p) {
    uint32_t a;
    asm("{ .reg .u64 t; cvta.to.shared.u64 t, %1; cvt.u32.u64 %0, t; }" : "=r"(a) : "l"(p));
    return a;
}
static __device__ __forceinline__ void ldsm4(uint32_t (&r)[4], uint32_t addr) {
    asm volatile("ldmatrix.sync.aligned.m8n8.x4.shared.b16 {%0,%1,%2,%3}, [%4];"
                 : "=r"(r[0]), "=r"(r[1]), "=r"(r[2]), "=r"(r[3]) : "r"(addr));
}
static __device__ __forceinline__ void mma16816(float* d, const uint32_t* a,
                                                uint32_t b0, uint32_t b1) {
    asm volatile(
        "mma.sync.aligned.m16n8k16.row.col.f32.bf16.bf16.f32 "
        "{%0,%1,%2,%3}, {%4,%5,%6,%7}, {%8,%9}, {%0,%1,%2,%3};"
        : "+f"(d[0]), "+f"(d[1]), "+f"(d[2]), "+f"(d[3])
        : "r"(a[0]), "r"(a[1]), "r"(a[2]), "r"(a[3]), "r"(b0), "r"(b1));
}
static __device__ __forceinline__ void cpasync16(uint32_t dst, const void* src) {
    asm volatile("cp.async.cg.shared.global [%0], [%1], 16;" :: "r"(dst), "l"(src));
}
// pack v0 (low half) / v1 (high half) into bf16x2 hi + residual lo
static __device__ __forceinline__ void packsplit(float v0, float v1,
                                                 uint32_t& wh, uint32_t& wl) {
    asm("cvt.rn.bf16x2.f32 %0, %1, %2;" : "=r"(wh) : "f"(v1), "f"(v0));
    float r0 = __uint_as_float(wh << 16);
    float r1 = __uint_as_float(wh & 0xFFFF0000u);
    float l0 = v0 - r0, l1 = v1 - r1;
    asm("cvt.rn.bf16x2.f32 %0, %1, %2;" : "=r"(wl) : "f"(l1), "f"(l0));
}

// ============================================================
// Prep: split fp32 weights into bf16 hi/lo and pack into ldmatrix-
// native tile order. Chunk j = 32-wide K slice. Tile t = ks*16+n16
// (512 B = one ldmatrix.x4 worth: 4 8x8 b16 matrices in lane order).
// Unit u (16 B) = matrix m = u>>3, ldmatrix row r = u&7:
//   unit holds W[kbase + (m&1)*8 + 0..7][nbase + (m>>1)*8 + r]
// ============================================================
__global__ void prep_kernel(const float* __restrict__ w0, const float* __restrict__ w1,
                            const float* __restrict__ w2, const float* __restrict__ w3,
                            const float* __restrict__ w4, const float* __restrict__ w5,
                            const float* __restrict__ w6, const float* __restrict__ w7) {
    int gidx = blockIdx.x * 256 + threadIdx.x;
    int cc = gidx & 7;
    int u  = (gidx >> 3) & 31;
    int t  = (gidx >> 8) & 31;
    int j  = gidx >> 13;
    if (j >= N_CHUNKS) return;
    int ks = t >> 4, n16 = t & 15, m = u >> 3, r = u & 7;
    int k_local = ks * 16 + (m & 1) * 8 + cc;
    int n = n16 * 16 + ((m >> 1) & 1) * 8 + r;

    const int starts[10] = {0, 2, 10, 18, 26, 28, 36, 44, 52, 60};
    int p = 0;
    while (j >= starts[p + 1]) ++p;
    int kg = (j - starts[p]) * 32 + k_local;

    float v = 0.0f;
    switch (p) {
        case 0: if (kg < 39) v = w0[kg * 256 + n]; break;
        case 1: v = w1[kg * 256 + n]; break;
        case 2: v = w2[kg * 256 + n]; break;
        case 3: v = w3[kg * 256 + n]; break;
        case 4: if (kg < 39) v = w4[kg * 256 + n]; break;
        case 5: v = w4[(39 + kg) * 256 + n]; break;
        case 6: v = w5[kg * 256 + n]; break;
        case 7: v = w6[kg * 256 + n]; break;
        default: v = w7[kg * 256 + n]; break;
    }
    __nv_bfloat16 hb = __float2bfloat16(v);
    __nv_bfloat16 lb = __float2bfloat16(v - __bfloat162float(hb));
    size_t addr = (size_t)j * CHUNK_BYTES + (size_t)t * 512 + (size_t)u * 16 + (size_t)cc * 2;
    *(__nv_bfloat16*)(g_wt + addr) = hb;
    *(__nv_bfloat16*)(g_wt + addr + HALF_BYTES) = lb;
}

// ============================================================
// Main kernel
// ============================================================
__global__ __launch_bounds__(THREADS, 1)
void mlp_kernel(const float* __restrict__ pts,
                const float* __restrict__ b0, const float* __restrict__ b1,
                const float* __restrict__ b2, const float* __restrict__ b3,
                const float* __restrict__ b4, const float* __restrict__ b5,
                const float* __restrict__ b6, const float* __restrict__ b7,
                const float* __restrict__ wsdf, const float* __restrict__ bsdf,
                float* __restrict__ out) {
    extern __shared__ unsigned char smem[];
    const uint32_t sb = smem_u32(smem);
    const int tid = threadIdx.x;
    const int lane = tid & 31;
    const int warp = tid >> 5;
    const int warpM = warp >> 2;   // 0..1
    const int warpN = warp & 3;    // 0..3
    const int base = blockIdx.x * TILE_M;

    ((float*)(smem + OFF_WSDF))[tid] = __ldg(wsdf + tid);

    // ---- harmonic embedding -> bf16 hi/lo, swizzled, K padded to 64 ----
    if (tid < TILE_M) {
        const float* pp = pts + (size_t)(base + tid) * 3;
        float co[3] = {pp[0], pp[1], pp[2]};
        float e[40];
        #pragma unroll
        for (int c = 0; c < 3; ++c) {
            float f = 1.0f;
            #pragma unroll
            for (int h = 0; h < 6; ++h) {
                float s, cs;
                sincosf(co[c] * f, &s, &cs);
                e[c * 6 + h] = s;
                e[18 + c * 6 + h] = cs;
                f *= 2.0f;
            }
        }
        e[36] = co[0]; e[37] = co[1]; e[38] = co[2]; e[39] = 0.0f;
        uint32_t ro = (uint32_t)tid * 128u;
        #pragma unroll
        for (int q = 0; q < 32; ++q) {
            float v0 = (2 * q < 40) ? e[2 * q] : 0.0f;
            float v1 = (2 * q + 1 < 40) ? e[2 * q + 1] : 0.0f;
            uint32_t wh, wl;
            packsplit(v0, v1, wh, wl);
            uint32_t off = ((uint32_t)q * 4u) ^ (((uint32_t)tid & 7u) << 4);
            *(uint32_t*)(smem + OFF_EMBH + ro + off) = wh;
            *(uint32_t*)(smem + OFF_EMBL + ro + off) = wl;
        }
    }

    // ---- prefetch chunk 0 ----
    {
        const unsigned char* src = g_wt + (size_t)tid * 16;
        uint32_t dst = sb + OFF_WB + (uint32_t)tid * 16;
        #pragma unroll
        for (int it = 0; it < 8; ++it) cpasync16(dst + it * 4096, src + (size_t)it * 4096);
        asm volatile("cp.async.commit_group;");
    }

    float acc[4][8][4];
    const float* biasTab[9] = {b0, b1, b2, b3, 0, b4, b5, b6, b7};
    const int NCH[9] = {2, 8, 8, 8, 2, 8, 8, 8, 8};
    int g = 0;

    #pragma unroll 1
    for (int ps = 0; ps < 9; ++ps) {
        const bool isEmb = (ps == 0 || ps == 4);
        if (ps != 5) {
            #pragma unroll
            for (int mt = 0; mt < 4; ++mt)
                #pragma unroll
                for (int nt = 0; nt < 8; ++nt)
                    #pragma unroll
                    for (int q = 0; q < 4; ++q) acc[mt][nt][q] = 0.0f;
        }
        const int nch = NCH[ps];
        const uint32_t srcH = sb + (isEmb ? OFF_EMBH : OFF_XH);
        const uint32_t srcL = sb + (isEmb ? OFF_EMBL : OFF_XL);
        const uint32_t pitch = isEmb ? 128u : 512u;

        #pragma unroll 1
        for (int c = 0; c < nch; ++c) {
            if (g + 1 < N_CHUNKS) {
                const unsigned char* src = g_wt + (size_t)(g + 1) * CHUNK_BYTES + (size_t)tid * 16;
                uint32_t dst = sb + OFF_WB + (uint32_t)((g + 1) & 1) * CHUNK_BYTES + (uint32_t)tid * 16;
                #pragma unroll
                for (int it = 0; it < 8; ++it) cpasync16(dst + it * 4096, src + (size_t)it * 4096);
                asm volatile("cp.async.commit_group;");
                asm volatile("cp.async.wait_group 1;" ::: "memory");
            } else {
                asm volatile("cp.async.wait_group 0;" ::: "memory");
            }
            __syncthreads();
            const uint32_t wb = sb + OFF_WB + (uint32_t)(g & 1) * CHUNK_BYTES;

            #pragma unroll
            for (int ks = 0; ks < 2; ++ks) {
                const int kb = c * 32 + ks * 16;
                uint32_t ah[4][4], al[4][4];
                {
                    const uint32_t row = (uint32_t)(warpM * 64 + (lane & 15));
                    const uint32_t swz = ((uint32_t)(kb + (lane >> 4) * 8) * 2u)
                                         ^ (((uint32_t)lane & 7u) << 4);
                    #pragma unroll
                    for (int mt = 0; mt < 4; ++mt) {
                        uint32_t ro = (row + mt * 16) * pitch + swz;
                        ldsm4(ah[mt], srcH + ro);
                        ldsm4(al[mt], srcL + ro);
                    }
                }
                uint32_t bh[4][4], bl[4][4];
                #pragma unroll
                for (int jj = 0; jj < 4; ++jj) {
                    uint32_t to = (uint32_t)(ks * 16 + warpN * 4 + jj) * 512u + (uint32_t)lane * 16u;
                    ldsm4(bh[jj], wb + to);
                    ldsm4(bl[jj], wb + HALF_BYTES + to);
                }
                #pragma unroll
                for (int mt = 0; mt < 4; ++mt)
                    #pragma unroll
                    for (int jj = 0; jj < 4; ++jj) {
                        mma16816(acc[mt][jj * 2],     ah[mt], bh[jj][0], bh[jj][1]);
                        mma16816(acc[mt][jj * 2],     ah[mt], bl[jj][0], bl[jj][1]);
                        mma16816(acc[mt][jj * 2],     al[mt], bh[jj][0], bh[jj][1]);
                        mma16816(acc[mt][jj * 2 + 1], ah[mt], bh[jj][2], bh[jj][3]);
                        mma16816(acc[mt][jj * 2 + 1], ah[mt], bl[jj][2], bl[jj][3]);
                        mma16816(acc[mt][jj * 2 + 1], al[mt], bh[jj][2], bh[jj][3]);
                    }
            }
            __syncthreads();
            ++g;
        }

        // ---- epilogue ----
        if (ps == 4) continue;  // accumulate skip-concat halves, no epilogue yet
        const float* bp = biasTab[ps];
        if (ps < 8) {
            #pragma unroll
            for (int mt = 0; mt < 4; ++mt) {
                const int r0 = warpM * 64 + mt * 16 + (lane >> 2);
                const int r1 = r0 + 8;
                #pragma unroll
                for (int nt = 0; nt < 8; ++nt) {
                    const int col = warpN * 64 + nt * 8 + (lane & 3) * 2;
                    const float bb0 = __ldg(bp + col);
                    const float bb1 = __ldg(bp + col + 1);
                    float v00 = fmaxf(acc[mt][nt][0] + bb0, 0.0f);
                    float v01 = fmaxf(acc[mt][nt][1] + bb1, 0.0f);
                    float v10 = fmaxf(acc[mt][nt][2] + bb0, 0.0f);
                    float v11 = fmaxf(acc[mt][nt][3] + bb1, 0.0f);
                    uint32_t wh, wl;
                    packsplit(v00, v01, wh, wl);
                    uint32_t o0 = (uint32_t)r0 * 512u
                                  + (((uint32_t)col * 2u) ^ (((uint32_t)r0 & 7u) << 4));
                    *(uint32_t*)(smem + OFF_XH + o0) = wh;
                    *(uint32_t*)(smem + OFF_XL + o0) = wl;
                    packsplit(v10, v11, wh, wl);
                    uint32_t o1 = (uint32_t)r1 * 512u
                                  + (((uint32_t)col * 2u) ^ (((uint32_t)r1 & 7u) << 4));
                    *(uint32_t*)(smem + OFF_XH + o1) = wh;
                    *(uint32_t*)(smem + OFF_XL + o1) = wl;
                }
            }
            __syncthreads();
        } else {
            // SDF head: relu(D + b7) . wsdf + bsdf
            const float* wS = (const float*)(smem + OFF_WSDF);
            float rp[8];
            #pragma unroll
            for (int i = 0; i < 8; ++i) rp[i] = 0.0f;
            #pragma unroll
            for (int mt = 0; mt < 4; ++mt)
                #pragma unroll
                for (int nt = 0; nt < 8; ++nt) {
                    const int col = warpN * 64 + nt * 8 + (lane & 3) * 2;
                    const float bb0 = __ldg(bp + col);
                    const float bb1 = __ldg(bp + col + 1);
                    const float w0v = wS[col], w1v = wS[col + 1];
                    rp[mt * 2]     += fmaxf(acc[mt][nt][0] + bb0, 0.0f) * w0v
                                    + fmaxf(acc[mt][nt][1] + bb1, 0.0f) * w1v;
                    rp[mt * 2 + 1] += fmaxf(acc[mt][nt][2] + bb0, 0.0f) * w0v
                                    + fmaxf(acc[mt][nt][3] + bb1, 0.0f) * w1v;
                }
            #pragma unroll
            for (int i = 0; i < 8; ++i) {
                rp[i] += __shfl_xor_sync(0xffffffffu, rp[i], 1);
                rp[i] += __shfl_xor_sync(0xffffffffu, rp[i], 2);
            }
            float* red = (float*)(smem + OFF_RED);
            if ((lane & 3) == 0) {
                #pragma unroll
                for (int mt = 0; mt < 4; ++mt) {
                    int row = warpM * 64 + mt * 16 + (lane >> 2);
                    red[row * 4 + warpN] = rp[mt * 2];
                    red[(row + 8) * 4 + warpN] = rp[mt * 2 + 1];
                }
            }
            __syncthreads();
            if (tid < TILE_M) {
                out[base + tid] = red[tid * 4] + red[tid * 4 + 1]
                                + red[tid * 4 + 2] + red[tid * 4 + 3] + __ldg(bsdf);
            }
        }
    }
}

// ============================================================
extern "C" void kernel_launch(void* const* d_in, const int* in_sizes, int n_in,
                              void* d_out, int out_size) {
    const float* pts = (const float*)d_in[0];
    const float* W[8];
    const float* B[8];
    for (int i = 0; i < 8; ++i) {
        W[i] = (const float*)d_in[1 + 2 * i];
        B[i] = (const float*)d_in[2 + 2 * i];
    }
    const float* wsdf = (const float*)d_in[17];
    const float* bsdf = (const float*)d_in[18];
    int n = in_sizes[0] / 3;     // 262144
    int grid = n / TILE_M;       // 2048

    prep_kernel<<<1920, 256>>>(W[0], W[1], W[2], W[3], W[4], W[5], W[6], W[7]);

    cudaFuncSetAttribute(mlp_kernel,
                         cudaFuncAttributeMaxDynamicSharedMemorySize, SMEM_BYTES);
    mlp_kernel<<<grid, THREADS, SMEM_BYTES>>>(
        pts, B[0], B[1], B[2], B[3], B[4], B[5], B[6], B[7],
        wsdf, bsdf, (float*)d_out);
}

// round 6
// speedup vs baseline: 3.4525x; 1.5803x over previous
#include <cuda_runtime.h>
#include <cuda_bf16.h>
#include <stdint.h>

// ============================================================
// NeuralSurface SDF MLP via mma.sync bf16 (hi/lo split, fp32 acc).
// Round 6: 2 CTAs/SM. M=64 points/CTA, 8 warps (2Mx4N), K chunks
// of 16 double-buffered (32KB ring), 109KB smem/CTA, 1 sync/chunk.
// ============================================================

#define THREADS 256
#define TILE_M  64

// smem byte offsets
#define OFF_XH   0            // X hi: 64 rows x 512 B
#define OFF_XL   32768        // X lo
#define OFF_WB   65536        // two 16 KB weight chunk buffers
#define OFF_EMBH 98304        // emb hi: 64 x 96 B (K=48, unswizzled)
#define OFF_EMBL 104448       // emb lo
#define OFF_RED  98304        // head reduction (aliases emb)
#define OFF_WSDF 110592       // 256 floats
#define SMEM_BYTES 111616

#define CHUNK_BYTES 16384     // K=16 slice: hi tiles 8KB + lo tiles 8KB
#define HALF_BYTES  8192
#define N_CHUNKS    118       // 3 + 16*3 + 3 + 16*4

__device__ __align__(128) unsigned char g_wt[(size_t)N_CHUNKS * CHUNK_BYTES];

// ---------------- helpers ----------------
static __device__ __forceinline__ uint32_t smem_u32(const void* p) {
    uint32_t a;
    asm("{ .reg .u64 t; cvta.to.shared.u64 t, %1; cvt.u32.u64 %0, t; }" : "=r"(a) : "l"(p));
    return a;
}
static __device__ __forceinline__ void ldsm4(uint32_t (&r)[4], uint32_t addr) {
    asm volatile("ldmatrix.sync.aligned.m8n8.x4.shared.b16 {%0,%1,%2,%3}, [%4];"
                 : "=r"(r[0]), "=r"(r[1]), "=r"(r[2]), "=r"(r[3]) : "r"(addr));
}
static __device__ __forceinline__ void mma16816(float* d, const uint32_t* a,
                                                uint32_t b0, uint32_t b1) {
    asm volatile(
        "mma.sync.aligned.m16n8k16.row.col.f32.bf16.bf16.f32 "
        "{%0,%1,%2,%3}, {%4,%5,%6,%7}, {%8,%9}, {%0,%1,%2,%3};"
        : "+f"(d[0]), "+f"(d[1]), "+f"(d[2]), "+f"(d[3])
        : "r"(a[0]), "r"(a[1]), "r"(a[2]), "r"(a[3]), "r"(b0), "r"(b1));
}
static __device__ __forceinline__ void cpasync16(uint32_t dst, const void* src) {
    asm volatile("cp.async.cg.shared.global [%0], [%1], 16;" :: "r"(dst), "l"(src));
}
static __device__ __forceinline__ void packsplit(float v0, float v1,
                                                 uint32_t& wh, uint32_t& wl) {
    asm("cvt.rn.bf16x2.f32 %0, %1, %2;" : "=r"(wh) : "f"(v1), "f"(v0));
    float r0 = __uint_as_float(wh << 16);
    float r1 = __uint_as_float(wh & 0xFFFF0000u);
    float l0 = v0 - r0, l1 = v1 - r1;
    asm("cvt.rn.bf16x2.f32 %0, %1, %2;" : "=r"(wl) : "f"(l1), "f"(l0));
}

// ============================================================
// Prep: split fp32 weights into bf16 hi/lo, pack into ldmatrix tile
// order. Chunk j = one K=16 slice of one pass. Tile t = n16 (0..15),
// 512 B each. Unit u (16 B): m = u>>3, r = u&7:
//   k_local = (m&1)*8 + cc,  n = n16*16 + ((m>>1)&1)*8 + r
// ============================================================
__global__ void prep_kernel(const float* __restrict__ w0, const float* __restrict__ w1,
                            const float* __restrict__ w2, const float* __restrict__ w3,
                            const float* __restrict__ w4, const float* __restrict__ w5,
                            const float* __restrict__ w6, const float* __restrict__ w7) {
    int gidx = blockIdx.x * 256 + threadIdx.x;
    int cc = gidx & 7;
    int u  = (gidx >> 3) & 31;
    int t  = (gidx >> 8) & 15;
    int j  = gidx >> 12;
    if (j >= N_CHUNKS) return;
    int m = u >> 3, r = u & 7;
    int k_local = (m & 1) * 8 + cc;
    int n = t * 16 + ((m >> 1) & 1) * 8 + r;

    const int starts[10] = {0, 3, 19, 35, 51, 54, 70, 86, 102, 118};
    int p = 0;
    while (j >= starts[p + 1]) ++p;
    int kg = (j - starts[p]) * 16 + k_local;

    float v = 0.0f;
    switch (p) {
        case 0: if (kg < 39) v = w0[kg * 256 + n]; break;
        case 1: v = w1[kg * 256 + n]; break;
        case 2: v = w2[kg * 256 + n]; break;
        case 3: v = w3[kg * 256 + n]; break;
        case 4: if (kg < 39) v = w4[kg * 256 + n]; break;
        case 5: v = w4[(39 + kg) * 256 + n]; break;
        case 6: v = w5[kg * 256 + n]; break;
        case 7: v = w6[kg * 256 + n]; break;
        default: v = w7[kg * 256 + n]; break;
    }
    __nv_bfloat16 hb = __float2bfloat16(v);
    __nv_bfloat16 lb = __float2bfloat16(v - __bfloat162float(hb));
    size_t addr = (size_t)j * CHUNK_BYTES + (size_t)t * 512 + (size_t)u * 16 + (size_t)cc * 2;
    *(__nv_bfloat16*)(g_wt + addr) = hb;
    *(__nv_bfloat16*)(g_wt + addr + HALF_BYTES) = lb;
}

// ============================================================
// Main kernel
// ============================================================
__global__ __launch_bounds__(THREADS, 2)
void mlp_kernel(const float* __restrict__ pts,
                const float* __restrict__ b0, const float* __restrict__ b1,
                const float* __restrict__ b2, const float* __restrict__ b3,
                const float* __restrict__ b4, const float* __restrict__ b5,
                const float* __restrict__ b6, const float* __restrict__ b7,
                const float* __restrict__ wsdf, const float* __restrict__ bsdf,
                float* __restrict__ out) {
    extern __shared__ unsigned char smem[];
    const uint32_t sb = smem_u32(smem);
    const int tid = threadIdx.x;
    const int lane = tid & 31;
    const int warp = tid >> 5;
    const int warpM = warp >> 2;   // 0..1 (32 rows each)
    const int warpN = warp & 3;    // 0..3 (64 cols each)
    const int base = blockIdx.x * TILE_M;

    // prefetch chunk 0 ASAP (overlaps embedding math)
    {
        const unsigned char* src = g_wt + (size_t)tid * 16;
        uint32_t dst = sb + OFF_WB + (uint32_t)tid * 16;
        #pragma unroll
        for (int it = 0; it < 4; ++it) cpasync16(dst + it * 4096, src + (size_t)it * 4096);
        asm volatile("cp.async.commit_group;");
    }

    ((float*)(smem + OFF_WSDF))[tid] = __ldg(wsdf + tid);

    // ---- harmonic embedding -> bf16 hi/lo, unswizzled, pitch 96 (K=48) ----
    if (tid < TILE_M) {
        const float* pp = pts + (size_t)(base + tid) * 3;
        float co[3] = {pp[0], pp[1], pp[2]};
        float e[48];
        #pragma unroll
        for (int c = 0; c < 3; ++c) {
            float f = 1.0f;
            #pragma unroll
            for (int h = 0; h < 6; ++h) {
                float s, cs;
                sincosf(co[c] * f, &s, &cs);
                e[c * 6 + h] = s;
                e[18 + c * 6 + h] = cs;
                f *= 2.0f;
            }
        }
        e[36] = co[0]; e[37] = co[1]; e[38] = co[2];
        #pragma unroll
        for (int q = 39; q < 48; ++q) e[q] = 0.0f;
        uint32_t ro = (uint32_t)tid * 96u;
        #pragma unroll
        for (int q = 0; q < 24; ++q) {
            uint32_t wh, wl;
            packsplit(e[2 * q], e[2 * q + 1], wh, wl);
            *(uint32_t*)(smem + OFF_EMBH + ro + q * 4) = wh;
            *(uint32_t*)(smem + OFF_EMBL + ro + q * 4) = wl;
        }
    }

    float acc[2][8][4];
    const float* biasTab[9] = {b0, b1, b2, b3, 0, b4, b5, b6, b7};
    const int NCH[9] = {3, 16, 16, 16, 3, 16, 16, 16, 16};
    int g = 0;

    #pragma unroll 1
    for (int ps = 0; ps < 9; ++ps) {
        const bool isEmb = (ps == 0 || ps == 4);
        if (ps != 5) {
            #pragma unroll
            for (int mt = 0; mt < 2; ++mt)
                #pragma unroll
                for (int nt = 0; nt < 8; ++nt)
                    #pragma unroll
                    for (int q = 0; q < 4; ++q) acc[mt][nt][q] = 0.0f;
        }
        const int nch = NCH[ps];
        const uint32_t srcH = sb + (isEmb ? OFF_EMBH : OFF_XH);
        const uint32_t srcL = sb + (isEmb ? OFF_EMBL : OFF_XL);

        #pragma unroll 1
        for (int c = 0; c < nch; ++c) {
            asm volatile("cp.async.wait_group 0;" ::: "memory");
            __syncthreads();   // chunk g visible; buffer (g+1)&1 reads (iter g-1) done;
                               // epilogue X writes (pass boundary) visible

            if (g + 1 < N_CHUNKS) {
                const unsigned char* src = g_wt + (size_t)(g + 1) * CHUNK_BYTES + (size_t)tid * 16;
                uint32_t dst = sb + OFF_WB + (uint32_t)((g + 1) & 1) * CHUNK_BYTES + (uint32_t)tid * 16;
                #pragma unroll
                for (int it = 0; it < 4; ++it) cpasync16(dst + it * 4096, src + (size_t)it * 4096);
                asm volatile("cp.async.commit_group;");
            }

            const uint32_t wb = sb + OFF_WB + (uint32_t)(g & 1) * CHUNK_BYTES;
            const int kb = c * 16;

            // A fragments (X or emb), 2 m-tiles, hi+lo
            uint32_t ah[2][4], al[2][4];
            if (isEmb) {
                const uint32_t row = (uint32_t)(warpM * 32 + (lane & 15));
                const uint32_t ko = (uint32_t)(kb + (lane >> 4) * 8) * 2u;
                #pragma unroll
                for (int mt = 0; mt < 2; ++mt) {
                    uint32_t ro = (row + mt * 16) * 96u + ko;
                    ldsm4(ah[mt], srcH + ro);
                    ldsm4(al[mt], srcL + ro);
                }
            } else {
                const uint32_t row = (uint32_t)(warpM * 32 + (lane & 15));
                const uint32_t swz = ((uint32_t)(kb + (lane >> 4) * 8) * 2u)
                                     ^ (((uint32_t)lane & 7u) << 4);
                #pragma unroll
                for (int mt = 0; mt < 2; ++mt) {
                    uint32_t ro = (row + mt * 16) * 512u + swz;
                    ldsm4(ah[mt], srcH + ro);
                    ldsm4(al[mt], srcL + ro);
                }
            }

            #pragma unroll
            for (int jj = 0; jj < 4; ++jj) {
                uint32_t bh[4], bl[4];
                uint32_t to = (uint32_t)(warpN * 4 + jj) * 512u + (uint32_t)lane * 16u;
                ldsm4(bh, wb + to);
                ldsm4(bl, wb + HALF_BYTES + to);
                #pragma unroll
                for (int mt = 0; mt < 2; ++mt) {
                    mma16816(acc[mt][jj * 2],     ah[mt], bh[0], bh[1]);
                    mma16816(acc[mt][jj * 2],     ah[mt], bl[0], bl[1]);
                    mma16816(acc[mt][jj * 2],     al[mt], bh[0], bh[1]);
                    mma16816(acc[mt][jj * 2 + 1], ah[mt], bh[2], bh[3]);
                    mma16816(acc[mt][jj * 2 + 1], ah[mt], bl[2], bl[3]);
                    mma16816(acc[mt][jj * 2 + 1], al[mt], bh[2], bh[3]);
                }
            }
            ++g;
        }

        // ---- epilogue ----
        if (ps == 4) continue;  // skip-concat: keep accumulating into same acc
        const float* bp = biasTab[ps];
        if (ps < 8) {
            // relu(D+b) -> bf16 hi/lo -> X smem (next chunk-start sync orders it)
            #pragma unroll
            for (int mt = 0; mt < 2; ++mt) {
                const int r0 = warpM * 32 + mt * 16 + (lane >> 2);
                const int r1 = r0 + 8;
                #pragma unroll
                for (int nt = 0; nt < 8; ++nt) {
                    const int col = warpN * 64 + nt * 8 + (lane & 3) * 2;
                    const float bb0 = __ldg(bp + col);
                    const float bb1 = __ldg(bp + col + 1);
                    float v00 = fmaxf(acc[mt][nt][0] + bb0, 0.0f);
                    float v01 = fmaxf(acc[mt][nt][1] + bb1, 0.0f);
                    float v10 = fmaxf(acc[mt][nt][2] + bb0, 0.0f);
                    float v11 = fmaxf(acc[mt][nt][3] + bb1, 0.0f);
                    uint32_t wh, wl;
                    packsplit(v00, v01, wh, wl);
                    uint32_t o0 = (uint32_t)r0 * 512u
                                  + (((uint32_t)col * 2u) ^ (((uint32_t)r0 & 7u) << 4));
                    *(uint32_t*)(smem + OFF_XH + o0) = wh;
                    *(uint32_t*)(smem + OFF_XL + o0) = wl;
                    packsplit(v10, v11, wh, wl);
                    uint32_t o1 = (uint32_t)r1 * 512u
                                  + (((uint32_t)col * 2u) ^ (((uint32_t)r1 & 7u) << 4));
                    *(uint32_t*)(smem + OFF_XH + o1) = wh;
                    *(uint32_t*)(smem + OFF_XL + o1) = wl;
                }
            }
        } else {
            // SDF head: relu(D + b7) . wsdf + bsdf
            const float* wS = (const float*)(smem + OFF_WSDF);
            float rp[4] = {0.0f, 0.0f, 0.0f, 0.0f};
            #pragma unroll
            for (int mt = 0; mt < 2; ++mt)
                #pragma unroll
                for (int nt = 0; nt < 8; ++nt) {
                    const int col = warpN * 64 + nt * 8 + (lane & 3) * 2;
                    const float bb0 = __ldg(bp + col);
                    const float bb1 = __ldg(bp + col + 1);
                    const float w0v = wS[col], w1v = wS[col + 1];
                    rp[mt * 2]     += fmaxf(acc[mt][nt][0] + bb0, 0.0f) * w0v
                                    + fmaxf(acc[mt][nt][1] + bb1, 0.0f) * w1v;
                    rp[mt * 2 + 1] += fmaxf(acc[mt][nt][2] + bb0, 0.0f) * w0v
                                    + fmaxf(acc[mt][nt][3] + bb1, 0.0f) * w1v;
                }
            #pragma unroll
            for (int i = 0; i < 4; ++i) {
                rp[i] += __shfl_xor_sync(0xffffffffu, rp[i], 1);
                rp[i] += __shfl_xor_sync(0xffffffffu, rp[i], 2);
            }
            float* red = (float*)(smem + OFF_RED);
            __syncthreads();   // emb region no longer needed by anyone
            if ((lane & 3) == 0) {
                #pragma unroll
                for (int mt = 0; mt < 2; ++mt) {
                    int row = warpM * 32 + mt * 16 + (lane >> 2);
                    red[row * 4 + warpN] = rp[mt * 2];
                    red[(row + 8) * 4 + warpN] = rp[mt * 2 + 1];
                }
            }
            __syncthreads();
            if (tid < TILE_M) {
                out[base + tid] = red[tid * 4] + red[tid * 4 + 1]
                                + red[tid * 4 + 2] + red[tid * 4 + 3] + __ldg(bsdf);
            }
        }
    }
}

// ============================================================
extern "C" void kernel_launch(void* const* d_in, const int* in_sizes, int n_in,
                              void* d_out, int out_size) {
    const float* pts = (const float*)d_in[0];
    const float* W[8];
    const float* B[8];
    for (int i = 0; i < 8; ++i) {
        W[i] = (const float*)d_in[1 + 2 * i];
        B[i] = (const float*)d_in[2 + 2 * i];
    }
    const float* wsdf = (const float*)d_in[17];
    const float* bsdf = (const float*)d_in[18];
    int n = in_sizes[0] / 3;     // 262144
    int grid = n / TILE_M;       // 4096

    prep_kernel<<<1888, 256>>>(W[0], W[1], W[2], W[3], W[4], W[5], W[6], W[7]);

    cudaFuncSetAttribute(mlp_kernel,
                         cudaFuncAttributeMaxDynamicSharedMemorySize, SMEM_BYTES);
    mlp_kernel<<<grid, THREADS, SMEM_BYTES>>>(
        pts, B[0], B[1], B[2], B[3], B[4], B[5], B[6], B[7],
        wsdf, bsdf, (float*)d_out);
}

// round 9
// speedup vs baseline: 4.0063x; 1.1604x over previous
#include <cuda_runtime.h>
#include <cuda_bf16.h>
#include <stdint.h>

// ============================================================
// NeuralSurface SDF MLP via mma.sync bf16 (hi/lo split, fp32 acc).
// Round 7: B fragments pre-packed in per-lane mma register layout,
// fetched by direct LDG.128 (no smem ring, no cp.async, no per-chunk
// barriers — syncs only at pass boundaries). 2 CTAs/SM.
// ============================================================

#define THREADS 256
#define TILE_M  64

// smem byte offsets
#define OFF_XH   0            // X hi: 64 rows x 512 B (swizzled)
#define OFF_XL   32768        // X lo
#define OFF_EMBH 65536        // emb hi: 64 x 96 B (K=48, unswizzled)
#define OFF_EMBL 71680        // emb lo
#define OFF_RED  65536        // head reduction (aliases emb)
#define OFF_WSDF 77824        // 256 floats
#define SMEM_BYTES 78848

#define CHUNK_BYTES 16384     // K=16 slice: hi half 8KB + lo half 8KB
#define HALF_BYTES  8192
#define N_CHUNKS    118       // 3 + 16*3 + 3 + 16*4

__device__ __align__(128) unsigned char g_wt[(size_t)N_CHUNKS * CHUNK_BYTES];

// ---------------- helpers ----------------
static __device__ __forceinline__ uint32_t smem_u32(const void* p) {
    uint32_t a;
    asm("{ .reg .u64 t; cvta.to.shared.u64 t, %1; cvt.u32.u64 %0, t; }" : "=r"(a) : "l"(p));
    return a;
}
static __device__ __forceinline__ void ldsm4(uint32_t (&r)[4], uint32_t addr) {
    asm volatile("ldmatrix.sync.aligned.m8n8.x4.shared.b16 {%0,%1,%2,%3}, [%4];"
                 : "=r"(r[0]), "=r"(r[1]), "=r"(r[2]), "=r"(r[3]) : "r"(addr));
}
static __device__ __forceinline__ void mma16816(float* d, const uint32_t* a,
                                                uint32_t b0, uint32_t b1) {
    asm volatile(
        "mma.sync.aligned.m16n8k16.row.col.f32.bf16.bf16.f32 "
        "{%0,%1,%2,%3}, {%4,%5,%6,%7}, {%8,%9}, {%0,%1,%2,%3};"
        : "+f"(d[0]), "+f"(d[1]), "+f"(d[2]), "+f"(d[3])
        : "r"(a[0]), "r"(a[1]), "r"(a[2]), "r"(a[3]), "r"(b0), "r"(b1));
}
static __device__ __forceinline__ void packsplit(float v0, float v1,
                                                 uint32_t& wh, uint32_t& wl) {
    asm("cvt.rn.bf16x2.f32 %0, %1, %2;" : "=r"(wh) : "f"(v1), "f"(v0));
    float r0 = __uint_as_float(wh << 16);
    float r1 = __uint_as_float(wh & 0xFFFF0000u);
    float l0 = v0 - r0, l1 = v1 - r1;
    asm("cvt.rn.bf16x2.f32 %0, %1, %2;" : "=r"(wl) : "f"(l1), "f"(l0));
}
static __device__ __forceinline__ uint4 ldg128(const void* p) {
    uint4 v;
    asm volatile("ld.global.nc.v4.u32 {%0,%1,%2,%3}, [%4];"
                 : "=r"(v.x), "=r"(v.y), "=r"(v.z), "=r"(v.w) : "l"(p));
    return v;
}

// ============================================================
// Prep: split fp32 weights into bf16 hi/lo, pre-packed so that for
// chunk j (K=16 slice), n16-tile t, LANE l's 16 bytes at
//   j*CHUNK + t*512 + l*16
// are exactly the 4 mma B-fragment regs {b0,b1 of n-tile0; b0,b1 of
// n-tile1}. Word q (0..3): n = t*16 + (q>>1)*8 + (l>>2),
// k_local = (q&1)*8 + (l&3)*2, bf16x2 = (W[kg][n], W[kg+1][n]).
// ============================================================
__global__ void prep_kernel(const float* __restrict__ w0, const float* __restrict__ w1,
                            const float* __restrict__ w2, const float* __restrict__ w3,
                            const float* __restrict__ w4, const float* __restrict__ w5,
                            const float* __restrict__ w6, const float* __restrict__ w7) {
    int gidx = blockIdx.x * 256 + threadIdx.x;
    int q = gidx & 3;
    int l = (gidx >> 2) & 31;
    int t = (gidx >> 7) & 15;
    int j = gidx >> 11;
    if (j >= N_CHUNKS) return;

    int n = t * 16 + ((q >> 1) & 1) * 8 + (l >> 2);
    int k_local = (q & 1) * 8 + (l & 3) * 2;

    const int starts[10] = {0, 3, 19, 35, 51, 54, 70, 86, 102, 118};
    int p = 0;
    while (j >= starts[p + 1]) ++p;
    int kg = (j - starts[p]) * 16 + k_local;

    const float* W;
    int rowoff = 0, kmax = 1 << 30;
    switch (p) {
        case 0: W = w0; kmax = 39; break;
        case 1: W = w1; break;
        case 2: W = w2; break;
        case 3: W = w3; break;
        case 4: W = w4; kmax = 39; break;
        case 5: W = w4; rowoff = 39; break;
        case 6: W = w5; break;
        case 7: W = w6; break;
        default: W = w7; break;
    }
    float v0 = (kg < kmax) ? W[(rowoff + kg) * 256 + n] : 0.0f;
    float v1 = (kg + 1 < kmax) ? W[(rowoff + kg + 1) * 256 + n] : 0.0f;

    uint32_t wh, wl;
    packsplit(v0, v1, wh, wl);
    size_t addr = (size_t)j * CHUNK_BYTES + (size_t)t * 512 + (size_t)l * 16 + (size_t)q * 4;
    *(uint32_t*)(g_wt + addr) = wh;
    *(uint32_t*)(g_wt + addr + HALF_BYTES) = wl;
}

// ============================================================
// Main kernel
// ============================================================
__global__ __launch_bounds__(THREADS, 2)
void mlp_kernel(const float* __restrict__ pts,
                const float* __restrict__ b0, const float* __restrict__ b1,
                const float* __restrict__ b2, const float* __restrict__ b3,
                const float* __restrict__ b4, const float* __restrict__ b5,
                const float* __restrict__ b6, const float* __restrict__ b7,
                const float* __restrict__ wsdf, const float* __restrict__ bsdf,
                float* __restrict__ out) {
    extern __shared__ unsigned char smem[];
    const uint32_t sb = smem_u32(smem);
    const int tid = threadIdx.x;
    const int lane = tid & 31;
    const int warp = tid >> 5;
    const int warpM = warp >> 2;   // 0..1 (32 rows each)
    const int warpN = warp & 3;    // 0..3 (64 cols each)
    const int base = blockIdx.x * TILE_M;

    ((float*)(smem + OFF_WSDF))[tid] = __ldg(wsdf + tid);

    // ---- harmonic embedding -> bf16 hi/lo, pitch 96 (K padded to 48) ----
    if (tid < TILE_M) {
        const float* pp = pts + (size_t)(base + tid) * 3;
        float co[3] = {pp[0], pp[1], pp[2]};
        float e[48];
        #pragma unroll
        for (int c = 0; c < 3; ++c) {
            float f = 1.0f;
            #pragma unroll
            for (int h = 0; h < 6; ++h) {
                float s, cs;
                sincosf(co[c] * f, &s, &cs);
                e[c * 6 + h] = s;
                e[18 + c * 6 + h] = cs;
                f *= 2.0f;
            }
        }
        e[36] = co[0]; e[37] = co[1]; e[38] = co[2];
        #pragma unroll
        for (int q = 39; q < 48; ++q) e[q] = 0.0f;
        uint32_t ro = (uint32_t)tid * 96u;
        #pragma unroll
        for (int q = 0; q < 24; ++q) {
            uint32_t wh, wl;
            packsplit(e[2 * q], e[2 * q + 1], wh, wl);
            *(uint32_t*)(smem + OFF_EMBH + ro + q * 4) = wh;
            *(uint32_t*)(smem + OFF_EMBL + ro + q * 4) = wl;
        }
    }
    __syncthreads();   // emb + wsdf visible

    float acc[2][8][4];
    const float* biasTab[9] = {b0, b1, b2, b3, 0, b4, b5, b6, b7};
    const int NCH[9] = {3, 16, 16, 16, 3, 16, 16, 16, 16};
    int g = 0;

    // B fragment pointers: lane's 16B within (chunk, tile)
    const unsigned char* bbase = g_wt + (size_t)lane * 16 + (size_t)(warpN * 4) * 512;

    // prefetch first B fragment pair (g=0, jj=0)
    uint4 bhC = ldg128(bbase);
    uint4 blC = ldg128(bbase + HALF_BYTES);

    #pragma unroll 1
    for (int ps = 0; ps < 9; ++ps) {
        const bool isEmb = (ps == 0 || ps == 4);
        if (ps != 5) {
            #pragma unroll
            for (int mt = 0; mt < 2; ++mt)
                #pragma unroll
                for (int nt = 0; nt < 8; ++nt)
                    #pragma unroll
                    for (int q = 0; q < 4; ++q) acc[mt][nt][q] = 0.0f;
        }
        const int nch = NCH[ps];
        const uint32_t srcH = sb + (isEmb ? OFF_EMBH : OFF_XH);
        const uint32_t srcL = sb + (isEmb ? OFF_EMBL : OFF_XL);

        #pragma unroll 1
        for (int c = 0; c < nch; ++c) {
            const int kb = c * 16;

            // A fragments (X or emb), 2 m-tiles, hi+lo
            uint32_t ah[2][4], al[2][4];
            {
                const uint32_t row = (uint32_t)(warpM * 32 + (lane & 15));
                const uint32_t pitch = isEmb ? 96u : 512u;
                uint32_t ko = (uint32_t)(kb + (lane >> 4) * 8) * 2u;
                if (!isEmb) ko ^= (((uint32_t)lane & 7u) << 4);
                #pragma unroll
                for (int mt = 0; mt < 2; ++mt) {
                    uint32_t ro = (row + mt * 16) * pitch + ko;
                    ldsm4(ah[mt], srcH + ro);
                    ldsm4(al[mt], srcL + ro);
                }
            }

            #pragma unroll
            for (int jj = 0; jj < 4; ++jj) {
                // prefetch next (chunk, jj) B fragments
                int ng = g, nj = jj + 1;
                if (nj == 4) { nj = 0; if (ng + 1 < N_CHUNKS) ++ng; }
                const unsigned char* np = bbase + (size_t)ng * CHUNK_BYTES + (size_t)nj * 512;
                uint4 bhN = ldg128(np);
                uint4 blN = ldg128(np + HALF_BYTES);

                #pragma unroll
                for (int mt = 0; mt < 2; ++mt) {
                    mma16816(acc[mt][jj * 2],     ah[mt], bhC.x, bhC.y);
                    mma16816(acc[mt][jj * 2],     ah[mt], blC.x, blC.y);
                    mma16816(acc[mt][jj * 2],     al[mt], bhC.x, bhC.y);
                    mma16816(acc[mt][jj * 2 + 1], ah[mt], bhC.z, bhC.w);
                    mma16816(acc[mt][jj * 2 + 1], ah[mt], blC.z, blC.w);
                    mma16816(acc[mt][jj * 2 + 1], al[mt], bhC.z, bhC.w);
                }
                bhC = bhN; blC = blN;
            }
            ++g;
        }

        // ---- epilogue ----
        if (ps == 4) continue;  // skip-concat: keep accumulating
        const float* bp = biasTab[ps];
        if (ps < 8) {
            __syncthreads();   // all warps done reading X/emb before overwrite
            #pragma unroll
            for (int mt = 0; mt < 2; ++mt) {
                const int r0 = warpM * 32 + mt * 16 + (lane >> 2);
                const int r1 = r0 + 8;
                #pragma unroll
                for (int nt = 0; nt < 8; ++nt) {
                    const int col = warpN * 64 + nt * 8 + (lane & 3) * 2;
                    const float bb0 = __ldg(bp + col);
                    const float bb1 = __ldg(bp + col + 1);
                    float v00 = fmaxf(acc[mt][nt][0] + bb0, 0.0f);
                    float v01 = fmaxf(acc[mt][nt][1] + bb1, 0.0f);
                    float v10 = fmaxf(acc[mt][nt][2] + bb0, 0.0f);
                    float v11 = fmaxf(acc[mt][nt][3] + bb1, 0.0f);
                    uint32_t wh, wl;
                    packsplit(v00, v01, wh, wl);
                    uint32_t o0 = (uint32_t)r0 * 512u
                                  + (((uint32_t)col * 2u) ^ (((uint32_t)r0 & 7u) << 4));
                    *(uint32_t*)(smem + OFF_XH + o0) = wh;
                    *(uint32_t*)(smem + OFF_XL + o0) = wl;
                    packsplit(v10, v11, wh, wl);
                    uint32_t o1 = (uint32_t)r1 * 512u
                                  + (((uint32_t)col * 2u) ^ (((uint32_t)r1 & 7u) << 4));
                    *(uint32_t*)(smem + OFF_XH + o1) = wh;
                    *(uint32_t*)(smem + OFF_XL + o1) = wl;
                }
            }
            __syncthreads();   // X visible for next pass
        } else {
            // SDF head: relu(D + b7) . wsdf + bsdf
            const float* wS = (const float*)(smem + OFF_WSDF);
            float rp[4] = {0.0f, 0.0f, 0.0f, 0.0f};
            #pragma unroll
            for (int mt = 0; mt < 2; ++mt)
                #pragma unroll
                for (int nt = 0; nt < 8; ++nt) {
                    const int col = warpN * 64 + nt * 8 + (lane & 3) * 2;
                    const float bb0 = __ldg(bp + col);
                    const float bb1 = __ldg(bp + col + 1);
                    const float w0v = wS[col], w1v = wS[col + 1];
                    rp[mt * 2]     += fmaxf(acc[mt][nt][0] + bb0, 0.0f) * w0v
                                    + fmaxf(acc[mt][nt][1] + bb1, 0.0f) * w1v;
                    rp[mt * 2 + 1] += fmaxf(acc[mt][nt][2] + bb0, 0.0f) * w0v
                                    + fmaxf(acc[mt][nt][3] + bb1, 0.0f) * w1v;
                }
            #pragma unroll
            for (int i = 0; i < 4; ++i) {
                rp[i] += __shfl_xor_sync(0xffffffffu, rp[i], 1);
                rp[i] += __shfl_xor_sync(0xffffffffu, rp[i], 2);
            }
            float* red = (float*)(smem + OFF_RED);
            __syncthreads();   // emb region dead; reuse for reduction
            if ((lane & 3) == 0) {
                #pragma unroll
                for (int mt = 0; mt < 2; ++mt) {
                    int row = warpM * 32 + mt * 16 + (lane >> 2);
                    red[row * 4 + warpN] = rp[mt * 2];
                    red[(row + 8) * 4 + warpN] = rp[mt * 2 + 1];
                }
            }
            __syncthreads();
            if (tid < TILE_M) {
                out[base + tid] = red[tid * 4] + red[tid * 4 + 1]
                                + red[tid * 4 + 2] + red[tid * 4 + 3] + __ldg(bsdf);
            }
        }
    }
}

// ============================================================
extern "C" void kernel_launch(void* const* d_in, const int* in_sizes, int n_in,
                              void* d_out, int out_size) {
    const float* pts = (const float*)d_in[0];
    const float* W[8];
    const float* B[8];
    for (int i = 0; i < 8; ++i) {
        W[i] = (const float*)d_in[1 + 2 * i];
        B[i] = (const float*)d_in[2 + 2 * i];
    }
    const float* wsdf = (const float*)d_in[17];
    const float* bsdf = (const float*)d_in[18];
    int n = in_sizes[0] / 3;     // 262144
    int grid = n / TILE_M;       // 4096

    prep_kernel<<<944, 256>>>(W[0], W[1], W[2], W[3], W[4], W[5], W[6], W[7]);

    cudaFuncSetAttribute(mlp_kernel,
                         cudaFuncAttributeMaxDynamicSharedMemorySize, SMEM_BYTES);
    mlp_kernel<<<grid, THREADS, SMEM_BYTES>>>(
        pts, B[0], B[1], B[2], B[3], B[4], B[5], B[6], B[7],
        wsdf, bsdf, (float*)d_out);
}

// round 12
// speedup vs baseline: 4.1348x; 1.0321x over previous
#include <cuda_runtime.h>
#include <cuda_bf16.h>
#include <stdint.h>

// ============================================================
// NeuralSurface SDF MLP via mma.sync bf16 (hi/lo split, fp32 acc).
// Round 10 (re-run; prior attempt hit broker infra failure):
// parallel embedding prologue, per-half named barriers,
// immediate-offset B LDGs, smem-resident biases. 2 CTAs/SM.
// ============================================================

#define THREADS 256
#define TILE_M  64

// smem byte offsets
#define OFF_XH   0            // X hi: 64 rows x 512 B (swizzled)
#define OFF_XL   32768        // X lo
#define OFF_EMBH 65536        // emb hi: 64 x 96 B (K=48, unswizzled)
#define OFF_EMBL 71680        // emb lo
#define OFF_RED  65536        // head reduction (aliases emb)
#define OFF_BIAS 77824        // 8 x 256 floats
#define OFF_WSDF 86016        // 256 floats
#define SMEM_BYTES 87040

#define CHUNK_BYTES 16384     // K=16 slice: hi half 8KB + lo half 8KB
#define HALF_BYTES  8192
#define N_CHUNKS    118       // 3 + 16*3 + 3 + 16*4

__device__ __align__(128) unsigned char g_wt[(size_t)N_CHUNKS * CHUNK_BYTES];

// ---------------- helpers ----------------
static __device__ __forceinline__ uint32_t smem_u32(const void* p) {
    uint32_t a;
    asm("{ .reg .u64 t; cvta.to.shared.u64 t, %1; cvt.u32.u64 %0, t; }" : "=r"(a) : "l"(p));
    return a;
}
static __device__ __forceinline__ void ldsm4(uint32_t (&r)[4], uint32_t addr) {
    asm volatile("ldmatrix.sync.aligned.m8n8.x4.shared.b16 {%0,%1,%2,%3}, [%4];"
                 : "=r"(r[0]), "=r"(r[1]), "=r"(r[2]), "=r"(r[3]) : "r"(addr));
}
static __device__ __forceinline__ void mma16816(float* d, const uint32_t* a,
                                                uint32_t b0, uint32_t b1) {
    asm volatile(
        "mma.sync.aligned.m16n8k16.row.col.f32.bf16.bf16.f32 "
        "{%0,%1,%2,%3}, {%4,%5,%6,%7}, {%8,%9}, {%0,%1,%2,%3};"
        : "+f"(d[0]), "+f"(d[1]), "+f"(d[2]), "+f"(d[3])
        : "r"(a[0]), "r"(a[1]), "r"(a[2]), "r"(a[3]), "r"(b0), "r"(b1));
}
static __device__ __forceinline__ void packsplit(float v0, float v1,
                                                 uint32_t& wh, uint32_t& wl) {
    asm("cvt.rn.bf16x2.f32 %0, %1, %2;" : "=r"(wh) : "f"(v1), "f"(v0));
    float r0 = __uint_as_float(wh << 16);
    float r1 = __uint_as_float(wh & 0xFFFF0000u);
    float l0 = v0 - r0, l1 = v1 - r1;
    asm("cvt.rn.bf16x2.f32 %0, %1, %2;" : "=r"(wl) : "f"(l1), "f"(l0));
}
static __device__ __forceinline__ uint4 ldg128(const void* p) {
    uint4 v;
    asm volatile("ld.global.nc.v4.u32 {%0,%1,%2,%3}, [%4];"
                 : "=r"(v.x), "=r"(v.y), "=r"(v.z), "=r"(v.w) : "l"(p));
    return v;
}
static __device__ __forceinline__ void half_bar(int id) {
    asm volatile("bar.sync %0, 128;" :: "r"(id) : "memory");
}

// ============================================================
// Prep: split fp32 weights into bf16 hi/lo, pre-packed so that for
// chunk j (K=16 slice), n16-tile t, LANE l's 16 bytes at
//   j*CHUNK + t*512 + l*16
// are exactly the 4 mma B-fragment regs. Word q (0..3):
//   n = t*16 + (q>>1)*8 + (l>>2),  k_local = (q&1)*8 + (l&3)*2,
//   bf16x2 = (W[kg][n], W[kg+1][n]).
// ============================================================
__global__ void prep_kernel(const float* __restrict__ w0, const float* __restrict__ w1,
                            const float* __restrict__ w2, const float* __restrict__ w3,
                            const float* __restrict__ w4, const float* __restrict__ w5,
                            const float* __restrict__ w6, const float* __restrict__ w7) {
    int gidx = blockIdx.x * 256 + threadIdx.x;
    int q = gidx & 3;
    int l = (gidx >> 2) & 31;
    int t = (gidx >> 7) & 15;
    int j = gidx >> 11;
    if (j >= N_CHUNKS) return;

    int n = t * 16 + ((q >> 1) & 1) * 8 + (l >> 2);
    int k_local = (q & 1) * 8 + (l & 3) * 2;

    const int starts[10] = {0, 3, 19, 35, 51, 54, 70, 86, 102, 118};
    int p = 0;
    while (j >= starts[p + 1]) ++p;
    int kg = (j - starts[p]) * 16 + k_local;

    const float* W;
    int rowoff = 0, kmax = 1 << 30;
    switch (p) {
        case 0: W = w0; kmax = 39; break;
        case 1: W = w1; break;
        case 2: W = w2; break;
        case 3: W = w3; break;
        case 4: W = w4; kmax = 39; break;
        case 5: W = w4; rowoff = 39; break;
        case 6: W = w5; break;
        case 7: W = w6; break;
        default: W = w7; break;
    }
    float v0 = (kg < kmax) ? W[(rowoff + kg) * 256 + n] : 0.0f;
    float v1 = (kg + 1 < kmax) ? W[(rowoff + kg + 1) * 256 + n] : 0.0f;

    uint32_t wh, wl;
    packsplit(v0, v1, wh, wl);
    size_t addr = (size_t)j * CHUNK_BYTES + (size_t)t * 512 + (size_t)l * 16 + (size_t)q * 4;
    *(uint32_t*)(g_wt + addr) = wh;
    *(uint32_t*)(g_wt + addr + HALF_BYTES) = wl;
}

// ============================================================
// Main kernel
// ============================================================
__global__ __launch_bounds__(THREADS, 2)
void mlp_kernel(const float* __restrict__ pts,
                const float* __restrict__ b0, const float* __restrict__ b1,
                const float* __restrict__ b2, const float* __restrict__ b3,
                const float* __restrict__ b4, const float* __restrict__ b5,
                const float* __restrict__ b6, const float* __restrict__ b7,
                const float* __restrict__ wsdf, const float* __restrict__ bsdf,
                float* __restrict__ out) {
    extern __shared__ unsigned char smem[];
    const uint32_t sb = smem_u32(smem);
    const int tid = threadIdx.x;
    const int lane = tid & 31;
    const int warp = tid >> 5;
    const int warpM = warp >> 2;   // 0..1 (32 rows each)
    const int warpN = warp & 3;    // 0..3 (64 cols each)
    const int base = blockIdx.x * TILE_M;

    // B stream pointer for this warp (chunk 0) + first prefetch, issued
    // before the prologue so it overlaps the sincos math.
    const unsigned char* bp = g_wt + (size_t)(warpN * 4) * 512 + (size_t)lane * 16;
    uint4 bhC = ldg128(bp);
    uint4 blC = ldg128(bp + HALF_BYTES);

    // ---- biases + head weights to smem ----
    {
        float* biasS = (float*)(smem + OFF_BIAS);
        biasS[tid]            = __ldg(b0 + tid);
        biasS[tid + 256]      = __ldg(b1 + tid);
        biasS[tid + 512]      = __ldg(b2 + tid);
        biasS[tid + 768]      = __ldg(b3 + tid);
        biasS[tid + 1024]     = __ldg(b4 + tid);
        biasS[tid + 1280]     = __ldg(b5 + tid);
        biasS[tid + 1536]     = __ldg(b6 + tid);
        biasS[tid + 1792]     = __ldg(b7 + tid);
        ((float*)(smem + OFF_WSDF))[tid] = __ldg(wsdf + tid);
    }

    // ---- harmonic embedding, parallel over (point, coord) ----
    // tid = c*64 + p. c<3: 6 sincos for coordinate c of point p ->
    // sin words c*3..c*3+2, cos words 9+c*3..+2. c==3: xyz words 18,19
    // and zero words 20..23. Word w covers e[2w], e[2w+1]; pitch 96 B.
    {
        const int c = tid >> 6;
        const int p = tid & 63;
        const uint32_t ro = (uint32_t)p * 96u;
        if (c < 3) {
            float co = __ldg(pts + (size_t)(base + p) * 3 + c);
            float s[6], cs[6];
            float f = 1.0f;
            #pragma unroll
            for (int h = 0; h < 6; ++h) {
                sincosf(co * f, &s[h], &cs[h]);
                f *= 2.0f;
            }
            #pragma unroll
            for (int w = 0; w < 3; ++w) {
                uint32_t wh, wl;
                packsplit(s[2 * w], s[2 * w + 1], wh, wl);
                *(uint32_t*)(smem + OFF_EMBH + ro + (c * 3 + w) * 4) = wh;
                *(uint32_t*)(smem + OFF_EMBL + ro + (c * 3 + w) * 4) = wl;
                packsplit(cs[2 * w], cs[2 * w + 1], wh, wl);
                *(uint32_t*)(smem + OFF_EMBH + ro + (9 + c * 3 + w) * 4) = wh;
                *(uint32_t*)(smem + OFF_EMBL + ro + (9 + c * 3 + w) * 4) = wl;
            }
        } else {
            const float* pp = pts + (size_t)(base + p) * 3;
            float x = __ldg(pp), y = __ldg(pp + 1), z = __ldg(pp + 2);
            uint32_t wh, wl;
            packsplit(x, y, wh, wl);
            *(uint32_t*)(smem + OFF_EMBH + ro + 18 * 4) = wh;
            *(uint32_t*)(smem + OFF_EMBL + ro + 18 * 4) = wl;
            packsplit(z, 0.0f, wh, wl);
            *(uint32_t*)(smem + OFF_EMBH + ro + 19 * 4) = wh;
            *(uint32_t*)(smem + OFF_EMBL + ro + 19 * 4) = wl;
            #pragma unroll
            for (int w = 20; w < 24; ++w) {
                *(uint32_t*)(smem + OFF_EMBH + ro + w * 4) = 0u;
                *(uint32_t*)(smem + OFF_EMBL + ro + w * 4) = 0u;
            }
        }
    }
    __syncthreads();   // emb + biases + wsdf visible to all

    float acc[2][8][4];
    const int NCH[9] = {3, 16, 16, 16, 3, 16, 16, 16, 16};
    const int BIDX[9] = {0, 1, 2, 3, 0, 4, 5, 6, 7};
    int g = 0;

    #pragma unroll 1
    for (int ps = 0; ps < 9; ++ps) {
        const bool isEmb = (ps == 0 || ps == 4);
        if (ps != 5) {
            #pragma unroll
            for (int mt = 0; mt < 2; ++mt)
                #pragma unroll
                for (int nt = 0; nt < 8; ++nt)
                    #pragma unroll
                    for (int q = 0; q < 4; ++q) acc[mt][nt][q] = 0.0f;
        }
        const int nch = NCH[ps];
        const uint32_t srcH = sb + (isEmb ? OFF_EMBH : OFF_XH);
        const uint32_t srcL = sb + (isEmb ? OFF_EMBL : OFF_XL);

        #pragma unroll 1
        for (int c = 0; c < nch; ++c) {
            const unsigned char* bpn = (g + 1 < N_CHUNKS) ? (bp + CHUNK_BYTES) : bp;
            const int kb = c * 16;

            // A fragments (X or emb), 2 m-tiles, hi+lo
            uint32_t ah[2][4], al[2][4];
            {
                const uint32_t row = (uint32_t)(warpM * 32 + (lane & 15));
                const uint32_t pitch = isEmb ? 96u : 512u;
                uint32_t ko = (uint32_t)(kb + (lane >> 4) * 8) * 2u;
                if (!isEmb) ko ^= (((uint32_t)lane & 7u) << 4);
                #pragma unroll
                for (int mt = 0; mt < 2; ++mt) {
                    uint32_t ro = (row + mt * 16) * pitch + ko;
                    ldsm4(ah[mt], srcH + ro);
                    ldsm4(al[mt], srcL + ro);
                }
            }

            #pragma unroll
            for (int jj = 0; jj < 4; ++jj) {
                // prefetch next (chunk, jj) B fragments; [reg+imm] addressing
                const unsigned char* np = (jj < 3) ? (bp + (jj + 1) * 512) : bpn;
                uint4 bhN = ldg128(np);
                uint4 blN = ldg128(np + HALF_BYTES);

                #pragma unroll
                for (int mt = 0; mt < 2; ++mt) {
                    mma16816(acc[mt][jj * 2],     ah[mt], bhC.x, bhC.y);
                    mma16816(acc[mt][jj * 2],     ah[mt], blC.x, blC.y);
                    mma16816(acc[mt][jj * 2],     al[mt], bhC.x, bhC.y);
                    mma16816(acc[mt][jj * 2 + 1], ah[mt], bhC.z, bhC.w);
                    mma16816(acc[mt][jj * 2 + 1], ah[mt], blC.z, blC.w);
                    mma16816(acc[mt][jj * 2 + 1], al[mt], bhC.z, bhC.w);
                }
                bhC = bhN; blC = blN;
            }
            bp = bpn;
            ++g;
        }

        // ---- epilogue ----
        if (ps == 4) continue;  // skip-concat: keep accumulating
        const float* bS = (const float*)(smem + OFF_BIAS) + BIDX[ps] * 256;
        if (ps < 8) {
            // X rows [warpM*32, +32) are written and read only by this
            // 4-warp half -> named barrier over 128 threads suffices.
            half_bar(1 + warpM);   // half's reads of X/emb rows done
            #pragma unroll
            for (int mt = 0; mt < 2; ++mt) {
                const int r0 = warpM * 32 + mt * 16 + (lane >> 2);
                const int r1 = r0 + 8;
                #pragma unroll
                for (int nt = 0; nt < 8; ++nt) {
                    const int col = warpN * 64 + nt * 8 + (lane & 3) * 2;
                    const float bb0 = bS[col];
                    const float bb1 = bS[col + 1];
                    float v00 = fmaxf(acc[mt][nt][0] + bb0, 0.0f);
                    float v01 = fmaxf(acc[mt][nt][1] + bb1, 0.0f);
                    float v10 = fmaxf(acc[mt][nt][2] + bb0, 0.0f);
                    float v11 = fmaxf(acc[mt][nt][3] + bb1, 0.0f);
                    uint32_t wh, wl;
                    packsplit(v00, v01, wh, wl);
                    uint32_t o0 = (uint32_t)r0 * 512u
                                  + (((uint32_t)col * 2u) ^ (((uint32_t)r0 & 7u) << 4));
                    *(uint32_t*)(smem + OFF_XH + o0) = wh;
                    *(uint32_t*)(smem + OFF_XL + o0) = wl;
                    packsplit(v10, v11, wh, wl);
                    uint32_t o1 = (uint32_t)r1 * 512u
                                  + (((uint32_t)col * 2u) ^ (((uint32_t)r1 & 7u) << 4));
                    *(uint32_t*)(smem + OFF_XH + o1) = wh;
                    *(uint32_t*)(smem + OFF_XL + o1) = wl;
                }
            }
            half_bar(1 + warpM);   // writes visible to half before next pass
        } else {
            // SDF head: relu(D + b7) . wsdf + bsdf
            const float* wS = (const float*)(smem + OFF_WSDF);
            float rp[4] = {0.0f, 0.0f, 0.0f, 0.0f};
            #pragma unroll
            for (int mt = 0; mt < 2; ++mt)
                #pragma unroll
                for (int nt = 0; nt < 8; ++nt) {
                    const int col = warpN * 64 + nt * 8 + (lane & 3) * 2;
                    const float bb0 = bS[col];
                    const float bb1 = bS[col + 1];
                    const float w0v = wS[col], w1v = wS[col + 1];
                    rp[mt * 2]     += fmaxf(acc[mt][nt][0] + bb0, 0.0f) * w0v
                                    + fmaxf(acc[mt][nt][1] + bb1, 0.0f) * w1v;
                    rp[mt * 2 + 1] += fmaxf(acc[mt][nt][2] + bb0, 0.0f) * w0v
                                    + fmaxf(acc[mt][nt][3] + bb1, 0.0f) * w1v;
                }
            #pragma unroll
            for (int i = 0; i < 4; ++i) {
                rp[i] += __shfl_xor_sync(0xffffffffu, rp[i], 1);
                rp[i] += __shfl_xor_sync(0xffffffffu, rp[i], 2);
            }
            float* red = (float*)(smem + OFF_RED);
            __syncthreads();   // ALL warps past emb reads; reuse region
            if ((lane & 3) == 0) {
                #pragma unroll
                for (int mt = 0; mt < 2; ++mt) {
                    int row = warpM * 32 + mt * 16 + (lane >> 2);
                    red[row * 4 + warpN] = rp[mt * 2];
                    red[(row + 8) * 4 + warpN] = rp[mt * 2 + 1];
                }
            }
            __syncthreads();
            if (tid < TILE_M) {
                out[base + tid] = red[tid * 4] + red[tid * 4 + 1]
                                + red[tid * 4 + 2] + red[tid * 4 + 3] + __ldg(bsdf);
            }
        }
    }
}

// ============================================================
extern "C" void kernel_launch(void* const* d_in, const int* in_sizes, int n_in,
                              void* d_out, int out_size) {
    const float* pts = (const float*)d_in[0];
    const float* W[8];
    const float* B[8];
    for (int i = 0; i < 8; ++i) {
        W[i] = (const float*)d_in[1 + 2 * i];
        B[i] = (const float*)d_in[2 + 2 * i];
    }
    const float* wsdf = (const float*)d_in[17];
    const float* bsdf = (const float*)d_in[18];
    int n = in_sizes[0] / 3;     // 262144
    int grid = n / TILE_M;       // 4096

    prep_kernel<<<944, 256>>>(W[0], W[1], W[2], W[3], W[4], W[5], W[6], W[7]);

    cudaFuncSetAttribute(mlp_kernel,
                         cudaFuncAttributeMaxDynamicSharedMemorySize, SMEM_BYTES);
    mlp_kernel<<<grid, THREADS, SMEM_BYTES>>>(
        pts, B[0], B[1], B[2], B[3], B[4], B[5], B[6], B[7],
        wsdf, bsdf, (float*)d_out);
}

// round 13
// speedup vs baseline: 5.7475x; 1.3900x over previous
#include <cuda_runtime.h>
#include <cuda_fp16.h>
#include <stdint.h>

// ============================================================
// NeuralSurface SDF MLP via mma.sync fp16 (W single, A hi+lo split,
// fp32 acc). Round 13: 4 MMAs per (K16,n16) instead of 6; weight
// stream halved. 2 CTAs/SM, per-half named barriers, LDG B-frags.
// ============================================================

#define THREADS 256
#define TILE_M  64

// smem byte offsets
#define OFF_XH   0            // X hi: 64 rows x 512 B (swizzled)
#define OFF_XL   32768        // X lo
#define OFF_EMBH 65536        // emb hi: 64 x 96 B (K=48, unswizzled)
#define OFF_EMBL 71680        // emb lo
#define OFF_RED  65536        // head reduction (aliases emb)
#define OFF_BIAS 77824        // 8 x 256 floats
#define OFF_WSDF 86016        // 256 floats
#define SMEM_BYTES 87040

#define CHUNK_BYTES 8192      // K=16 slice, fp16 single: 16 tiles x 512 B
#define N_CHUNKS    118       // 3 + 16*3 + 3 + 16*4

__device__ __align__(128) unsigned char g_wt[(size_t)N_CHUNKS * CHUNK_BYTES];

// ---------------- helpers ----------------
static __device__ __forceinline__ uint32_t smem_u32(const void* p) {
    uint32_t a;
    asm("{ .reg .u64 t; cvta.to.shared.u64 t, %1; cvt.u32.u64 %0, t; }" : "=r"(a) : "l"(p));
    return a;
}
static __device__ __forceinline__ void ldsm4(uint32_t (&r)[4], uint32_t addr) {
    asm volatile("ldmatrix.sync.aligned.m8n8.x4.shared.b16 {%0,%1,%2,%3}, [%4];"
                 : "=r"(r[0]), "=r"(r[1]), "=r"(r[2]), "=r"(r[3]) : "r"(addr));
}
static __device__ __forceinline__ void mma16816(float* d, const uint32_t* a,
                                                uint32_t b0, uint32_t b1) {
    asm volatile(
        "mma.sync.aligned.m16n8k16.row.col.f32.f16.f16.f32 "
        "{%0,%1,%2,%3}, {%4,%5,%6,%7}, {%8,%9}, {%0,%1,%2,%3};"
        : "+f"(d[0]), "+f"(d[1]), "+f"(d[2]), "+f"(d[3])
        : "r"(a[0]), "r"(a[1]), "r"(a[2]), "r"(a[3]), "r"(b0), "r"(b1));
}
// pack (v0 -> low half, v1 -> high half) into fp16x2 hi + fp16x2 residual lo
static __device__ __forceinline__ void packsplit16(float v0, float v1,
                                                   uint32_t& wh, uint32_t& wl) {
    __half2 h = __floats2half2_rn(v0, v1);
    wh = *reinterpret_cast<uint32_t*>(&h);
    float2 r = __half22float2(h);
    __half2 l = __floats2half2_rn(v0 - r.x, v1 - r.y);
    wl = *reinterpret_cast<uint32_t*>(&l);
}
static __device__ __forceinline__ uint4 ldg128(const void* p) {
    uint4 v;
    asm volatile("ld.global.nc.v4.u32 {%0,%1,%2,%3}, [%4];"
                 : "=r"(v.x), "=r"(v.y), "=r"(v.z), "=r"(v.w) : "l"(p));
    return v;
}
static __device__ __forceinline__ void half_bar(int id) {
    asm volatile("bar.sync %0, 128;" :: "r"(id) : "memory");
}

// ============================================================
// Prep: fp32 weights -> single fp16, pre-packed in per-lane mma
// B-fragment layout. Chunk j (K=16 slice), tile t (n16), lane l's
// 16 B at j*CHUNK + t*512 + l*16. Word q (0..3):
//   n = t*16 + (q>>1)*8 + (l>>2),  k_local = (q&1)*8 + (l&3)*2,
//   f16x2 = (W[kg][n], W[kg+1][n]).
// ============================================================
__global__ void prep_kernel(const float* __restrict__ w0, const float* __restrict__ w1,
                            const float* __restrict__ w2, const float* __restrict__ w3,
                            const float* __restrict__ w4, const float* __restrict__ w5,
                            const float* __restrict__ w6, const float* __restrict__ w7) {
    int gidx = blockIdx.x * 256 + threadIdx.x;
    int q = gidx & 3;
    int l = (gidx >> 2) & 31;
    int t = (gidx >> 7) & 15;
    int j = gidx >> 11;
    if (j >= N_CHUNKS) return;

    int n = t * 16 + ((q >> 1) & 1) * 8 + (l >> 2);
    int k_local = (q & 1) * 8 + (l & 3) * 2;

    const int starts[10] = {0, 3, 19, 35, 51, 54, 70, 86, 102, 118};
    int p = 0;
    while (j >= starts[p + 1]) ++p;
    int kg = (j - starts[p]) * 16 + k_local;

    const float* W;
    int rowoff = 0, kmax = 1 << 30;
    switch (p) {
        case 0: W = w0; kmax = 39; break;
        case 1: W = w1; break;
        case 2: W = w2; break;
        case 3: W = w3; break;
        case 4: W = w4; kmax = 39; break;
        case 5: W = w4; rowoff = 39; break;
        case 6: W = w5; break;
        case 7: W = w6; break;
        default: W = w7; break;
    }
    float v0 = (kg < kmax) ? W[(rowoff + kg) * 256 + n] : 0.0f;
    float v1 = (kg + 1 < kmax) ? W[(rowoff + kg + 1) * 256 + n] : 0.0f;

    __half2 h = __floats2half2_rn(v0, v1);
    size_t addr = (size_t)j * CHUNK_BYTES + (size_t)t * 512 + (size_t)l * 16 + (size_t)q * 4;
    *(uint32_t*)(g_wt + addr) = *reinterpret_cast<uint32_t*>(&h);
}

// ============================================================
// Main kernel
// ============================================================
__global__ __launch_bounds__(THREADS, 2)
void mlp_kernel(const float* __restrict__ pts,
                const float* __restrict__ b0, const float* __restrict__ b1,
                const float* __restrict__ b2, const float* __restrict__ b3,
                const float* __restrict__ b4, const float* __restrict__ b5,
                const float* __restrict__ b6, const float* __restrict__ b7,
                const float* __restrict__ wsdf, const float* __restrict__ bsdf,
                float* __restrict__ out) {
    extern __shared__ unsigned char smem[];
    const uint32_t sb = smem_u32(smem);
    const int tid = threadIdx.x;
    const int lane = tid & 31;
    const int warp = tid >> 5;
    const int warpM = warp >> 2;   // 0..1 (32 rows each)
    const int warpN = warp & 3;    // 0..3 (64 cols each)
    const int base = blockIdx.x * TILE_M;

    // B stream pointer (chunk 0) + first prefetch, overlaps prologue.
    const unsigned char* bp = g_wt + (size_t)(warpN * 4) * 512 + (size_t)lane * 16;
    uint4 bC = ldg128(bp);

    // ---- biases + head weights to smem ----
    {
        float* biasS = (float*)(smem + OFF_BIAS);
        biasS[tid]            = __ldg(b0 + tid);
        biasS[tid + 256]      = __ldg(b1 + tid);
        biasS[tid + 512]      = __ldg(b2 + tid);
        biasS[tid + 768]      = __ldg(b3 + tid);
        biasS[tid + 1024]     = __ldg(b4 + tid);
        biasS[tid + 1280]     = __ldg(b5 + tid);
        biasS[tid + 1536]     = __ldg(b6 + tid);
        biasS[tid + 1792]     = __ldg(b7 + tid);
        ((float*)(smem + OFF_WSDF))[tid] = __ldg(wsdf + tid);
    }

    // ---- harmonic embedding, parallel over (point, coord) ----
    {
        const int c = tid >> 6;
        const int p = tid & 63;
        const uint32_t ro = (uint32_t)p * 96u;
        if (c < 3) {
            float co = __ldg(pts + (size_t)(base + p) * 3 + c);
            float s[6], cs[6];
            float f = 1.0f;
            #pragma unroll
            for (int h = 0; h < 6; ++h) {
                sincosf(co * f, &s[h], &cs[h]);
                f *= 2.0f;
            }
            #pragma unroll
            for (int w = 0; w < 3; ++w) {
                uint32_t wh, wl;
                packsplit16(s[2 * w], s[2 * w + 1], wh, wl);
                *(uint32_t*)(smem + OFF_EMBH + ro + (c * 3 + w) * 4) = wh;
                *(uint32_t*)(smem + OFF_EMBL + ro + (c * 3 + w) * 4) = wl;
                packsplit16(cs[2 * w], cs[2 * w + 1], wh, wl);
                *(uint32_t*)(smem + OFF_EMBH + ro + (9 + c * 3 + w) * 4) = wh;
                *(uint32_t*)(smem + OFF_EMBL + ro + (9 + c * 3 + w) * 4) = wl;
            }
        } else {
            const float* pp = pts + (size_t)(base + p) * 3;
            float x = __ldg(pp), y = __ldg(pp + 1), z = __ldg(pp + 2);
            uint32_t wh, wl;
            packsplit16(x, y, wh, wl);
            *(uint32_t*)(smem + OFF_EMBH + ro + 18 * 4) = wh;
            *(uint32_t*)(smem + OFF_EMBL + ro + 18 * 4) = wl;
            packsplit16(z, 0.0f, wh, wl);
            *(uint32_t*)(smem + OFF_EMBH + ro + 19 * 4) = wh;
            *(uint32_t*)(smem + OFF_EMBL + ro + 19 * 4) = wl;
            #pragma unroll
            for (int w = 20; w < 24; ++w) {
                *(uint32_t*)(smem + OFF_EMBH + ro + w * 4) = 0u;
                *(uint32_t*)(smem + OFF_EMBL + ro + w * 4) = 0u;
            }
        }
    }
    __syncthreads();   // emb + biases + wsdf visible to all

    float acc[2][8][4];
    const int NCH[9] = {3, 16, 16, 16, 3, 16, 16, 16, 16};
    const int BIDX[9] = {0, 1, 2, 3, 0, 4, 5, 6, 7};
    int g = 0;

    #pragma unroll 1
    for (int ps = 0; ps < 9; ++ps) {
        const bool isEmb = (ps == 0 || ps == 4);
        if (ps != 5) {
            #pragma unroll
            for (int mt = 0; mt < 2; ++mt)
                #pragma unroll
                for (int nt = 0; nt < 8; ++nt)
                    #pragma unroll
                    for (int q = 0; q < 4; ++q) acc[mt][nt][q] = 0.0f;
        }
        const int nch = NCH[ps];
        const uint32_t srcH = sb + (isEmb ? OFF_EMBH : OFF_XH);
        const uint32_t srcL = sb + (isEmb ? OFF_EMBL : OFF_XL);

        #pragma unroll 1
        for (int c = 0; c < nch; ++c) {
            const unsigned char* bpn = (g + 1 < N_CHUNKS) ? (bp + CHUNK_BYTES) : bp;
            const int kb = c * 16;

            // A fragments (X or emb), 2 m-tiles, hi+lo
            uint32_t ah[2][4], al[2][4];
            {
                const uint32_t row = (uint32_t)(warpM * 32 + (lane & 15));
                const uint32_t pitch = isEmb ? 96u : 512u;
                uint32_t ko = (uint32_t)(kb + (lane >> 4) * 8) * 2u;
                if (!isEmb) ko ^= (((uint32_t)lane & 7u) << 4);
                #pragma unroll
                for (int mt = 0; mt < 2; ++mt) {
                    uint32_t ro = (row + mt * 16) * pitch + ko;
                    ldsm4(ah[mt], srcH + ro);
                    ldsm4(al[mt], srcL + ro);
                }
            }

            #pragma unroll
            for (int jj = 0; jj < 4; ++jj) {
                // prefetch next (chunk, jj) B fragment; [reg+imm] addressing
                const unsigned char* np = (jj < 3) ? (bp + (jj + 1) * 512) : bpn;
                uint4 bN = ldg128(np);

                #pragma unroll
                for (int mt = 0; mt < 2; ++mt) {
                    mma16816(acc[mt][jj * 2],     ah[mt], bC.x, bC.y);
                    mma16816(acc[mt][jj * 2],     al[mt], bC.x, bC.y);
                    mma16816(acc[mt][jj * 2 + 1], ah[mt], bC.z, bC.w);
                    mma16816(acc[mt][jj * 2 + 1], al[mt], bC.z, bC.w);
                }
                bC = bN;
            }
            bp = bpn;
            ++g;
        }

        // ---- epilogue ----
        if (ps == 4) continue;  // skip-concat: keep accumulating
        const float* bS = (const float*)(smem + OFF_BIAS) + BIDX[ps] * 256;
        if (ps < 8) {
            // X rows [warpM*32, +32) touched only by this 4-warp half.
            half_bar(1 + warpM);   // half's reads of X/emb rows done
            #pragma unroll
            for (int mt = 0; mt < 2; ++mt) {
                const int r0 = warpM * 32 + mt * 16 + (lane >> 2);
                const int r1 = r0 + 8;
                #pragma unroll
                for (int nt = 0; nt < 8; ++nt) {
                    const int col = warpN * 64 + nt * 8 + (lane & 3) * 2;
                    const float bb0 = bS[col];
                    const float bb1 = bS[col + 1];
                    float v00 = fmaxf(acc[mt][nt][0] + bb0, 0.0f);
                    float v01 = fmaxf(acc[mt][nt][1] + bb1, 0.0f);
                    float v10 = fmaxf(acc[mt][nt][2] + bb0, 0.0f);
                    float v11 = fmaxf(acc[mt][nt][3] + bb1, 0.0f);
                    uint32_t wh, wl;
                    packsplit16(v00, v01, wh, wl);
                    uint32_t o0 = (uint32_t)r0 * 512u
                                  + (((uint32_t)col * 2u) ^ (((uint32_t)r0 & 7u) << 4));
                    *(uint32_t*)(smem + OFF_XH + o0) = wh;
                    *(uint32_t*)(smem + OFF_XL + o0) = wl;
                    packsplit16(v10, v11, wh, wl);
                    uint32_t o1 = (uint32_t)r1 * 512u
                                  + (((uint32_t)col * 2u) ^ (((uint32_t)r1 & 7u) << 4));
                    *(uint32_t*)(smem + OFF_XH + o1) = wh;
                    *(uint32_t*)(smem + OFF_XL + o1) = wl;
                }
            }
            half_bar(1 + warpM);   // writes visible to half before next pass
        } else {
            // SDF head: relu(D + b7) . wsdf + bsdf
            const float* wS = (const float*)(smem + OFF_WSDF);
            float rp[4] = {0.0f, 0.0f, 0.0f, 0.0f};
            #pragma unroll
            for (int mt = 0; mt < 2; ++mt)
                #pragma unroll
                for (int nt = 0; nt < 8; ++nt) {
                    const int col = warpN * 64 + nt * 8 + (lane & 3) * 2;
                    const float bb0 = bS[col];
                    const float bb1 = bS[col + 1];
                    const float w0v = wS[col], w1v = wS[col + 1];
                    rp[mt * 2]     += fmaxf(acc[mt][nt][0] + bb0, 0.0f) * w0v
                                    + fmaxf(acc[mt][nt][1] + bb1, 0.0f) * w1v;
                    rp[mt * 2 + 1] += fmaxf(acc[mt][nt][2] + bb0, 0.0f) * w0v
                                    + fmaxf(acc[mt][nt][3] + bb1, 0.0f) * w1v;
                }
            #pragma unroll
            for (int i = 0; i < 4; ++i) {
                rp[i] += __shfl_xor_sync(0xffffffffu, rp[i], 1);
                rp[i] += __shfl_xor_sync(0xffffffffu, rp[i], 2);
            }
            float* red = (float*)(smem + OFF_RED);
            __syncthreads();   // ALL warps past emb reads; reuse region
            if ((lane & 3) == 0) {
                #pragma unroll
                for (int mt = 0; mt < 2; ++mt) {
                    int row = warpM * 32 + mt * 16 + (lane >> 2);
                    red[row * 4 + warpN] = rp[mt * 2];
                    red[(row + 8) * 4 + warpN] = rp[mt * 2 + 1];
                }
            }
            __syncthreads();
            if (tid < TILE_M) {
                out[base + tid] = red[tid * 4] + red[tid * 4 + 1]
                                + red[tid * 4 + 2] + red[tid * 4 + 3] + __ldg(bsdf);
            }
        }
    }
}

// ============================================================
extern "C" void kernel_launch(void* const* d_in, const int* in_sizes, int n_in,
                              void* d_out, int out_size) {
    const float* pts = (const float*)d_in[0];
    const float* W[8];
    const float* B[8];
    for (int i = 0; i < 8; ++i) {
        W[i] = (const float*)d_in[1 + 2 * i];
        B[i] = (const float*)d_in[2 + 2 * i];
    }
    const float* wsdf = (const float*)d_in[17];
    const float* bsdf = (const float*)d_in[18];
    int n = in_sizes[0] / 3;     // 262144
    int grid = n / TILE_M;       // 4096

    prep_kernel<<<944, 256>>>(W[0], W[1], W[2], W[3], W[4], W[5], W[6], W[7]);

    cudaFuncSetAttribute(mlp_kernel,
                         cudaFuncAttributeMaxDynamicSharedMemorySize, SMEM_BYTES);
    mlp_kernel<<<grid, THREADS, SMEM_BYTES>>>(
        pts, B[0], B[1], B[2], B[3], B[4], B[5], B[6], B[7],
        wsdf, bsdf, (float*)d_out);
}

// round 14
// speedup vs baseline: 5.7678x; 1.0035x over previous
#include <cuda_runtime.h>
#include <cuda_fp16.h>
#include <stdint.h>

// ============================================================
// NeuralSurface SDF MLP via mma.sync fp16 (W single, A hi+lo split,
// fp32 acc). Round 14: branchless padded B stream, strength-reduced
// A-fragment addressing. 2 CTAs/SM, per-half named barriers.
// ============================================================

#define THREADS 256
#define TILE_M  64

// smem byte offsets
#define OFF_XH   0            // X hi: 64 rows x 512 B (swizzled)
#define OFF_XL   32768        // X lo
#define OFF_EMBH 65536        // emb hi: 64 x 96 B (K=48, unswizzled)
#define OFF_EMBL 71680        // emb lo
#define OFF_RED  65536        // head reduction (aliases emb)
#define OFF_BIAS 77824        // 8 x 256 floats
#define OFF_WSDF 86016        // 256 floats
#define SMEM_BYTES 87040

#define CHUNK_BYTES 8192      // K=16 slice, fp16 single: 16 tiles x 512 B
#define N_CHUNKS    118       // 3 + 16*3 + 3 + 16*4

// +1 pad chunk: the always-ahead prefetch reads it on the last chunk
// (value never used) so the stream pointer advance is branchless.
__device__ __align__(128) unsigned char g_wt[(size_t)(N_CHUNKS + 1) * CHUNK_BYTES];

// ---------------- helpers ----------------
static __device__ __forceinline__ uint32_t smem_u32(const void* p) {
    uint32_t a;
    asm("{ .reg .u64 t; cvta.to.shared.u64 t, %1; cvt.u32.u64 %0, t; }" : "=r"(a) : "l"(p));
    return a;
}
static __device__ __forceinline__ void ldsm4(uint32_t (&r)[4], uint32_t addr) {
    asm volatile("ldmatrix.sync.aligned.m8n8.x4.shared.b16 {%0,%1,%2,%3}, [%4];"
                 : "=r"(r[0]), "=r"(r[1]), "=r"(r[2]), "=r"(r[3]) : "r"(addr));
}
static __device__ __forceinline__ void mma16816(float* d, const uint32_t* a,
                                                uint32_t b0, uint32_t b1) {
    asm volatile(
        "mma.sync.aligned.m16n8k16.row.col.f32.f16.f16.f32 "
        "{%0,%1,%2,%3}, {%4,%5,%6,%7}, {%8,%9}, {%0,%1,%2,%3};"
        : "+f"(d[0]), "+f"(d[1]), "+f"(d[2]), "+f"(d[3])
        : "r"(a[0]), "r"(a[1]), "r"(a[2]), "r"(a[3]), "r"(b0), "r"(b1));
}
// pack (v0 -> low half, v1 -> high half) into fp16x2 hi + fp16x2 residual lo
static __device__ __forceinline__ void packsplit16(float v0, float v1,
                                                   uint32_t& wh, uint32_t& wl) {
    __half2 h = __floats2half2_rn(v0, v1);
    wh = *reinterpret_cast<uint32_t*>(&h);
    float2 r = __half22float2(h);
    __half2 l = __floats2half2_rn(v0 - r.x, v1 - r.y);
    wl = *reinterpret_cast<uint32_t*>(&l);
}
static __device__ __forceinline__ uint4 ldg128(const void* p) {
    uint4 v;
    asm volatile("ld.global.nc.v4.u32 {%0,%1,%2,%3}, [%4];"
                 : "=r"(v.x), "=r"(v.y), "=r"(v.z), "=r"(v.w) : "l"(p));
    return v;
}
static __device__ __forceinline__ void half_bar(int id) {
    asm volatile("bar.sync %0, 128;" :: "r"(id) : "memory");
}

// ============================================================
// Prep: fp32 weights -> single fp16, pre-packed in per-lane mma
// B-fragment layout. Chunk j (K=16 slice), tile t (n16), lane l's
// 16 B at j*CHUNK + t*512 + l*16. Word q (0..3):
//   n = t*16 + (q>>1)*8 + (l>>2),  k_local = (q&1)*8 + (l&3)*2,
//   f16x2 = (W[kg][n], W[kg+1][n]).
// ============================================================
__global__ void prep_kernel(const float* __restrict__ w0, const float* __restrict__ w1,
                            const float* __restrict__ w2, const float* __restrict__ w3,
                            const float* __restrict__ w4, const float* __restrict__ w5,
                            const float* __restrict__ w6, const float* __restrict__ w7) {
    int gidx = blockIdx.x * 256 + threadIdx.x;
    int q = gidx & 3;
    int l = (gidx >> 2) & 31;
    int t = (gidx >> 7) & 15;
    int j = gidx >> 11;
    if (j >= N_CHUNKS) return;

    int n = t * 16 + ((q >> 1) & 1) * 8 + (l >> 2);
    int k_local = (q & 1) * 8 + (l & 3) * 2;

    const int starts[10] = {0, 3, 19, 35, 51, 54, 70, 86, 102, 118};
    int p = 0;
    while (j >= starts[p + 1]) ++p;
    int kg = (j - starts[p]) * 16 + k_local;

    const float* W;
    int rowoff = 0, kmax = 1 << 30;
    switch (p) {
        case 0: W = w0; kmax = 39; break;
        case 1: W = w1; break;
        case 2: W = w2; break;
        case 3: W = w3; break;
        case 4: W = w4; kmax = 39; break;
        case 5: W = w4; rowoff = 39; break;
        case 6: W = w5; break;
        case 7: W = w6; break;
        default: W = w7; break;
    }
    float v0 = (kg < kmax) ? W[(rowoff + kg) * 256 + n] : 0.0f;
    float v1 = (kg + 1 < kmax) ? W[(rowoff + kg + 1) * 256 + n] : 0.0f;

    __half2 h = __floats2half2_rn(v0, v1);
    size_t addr = (size_t)j * CHUNK_BYTES + (size_t)t * 512 + (size_t)l * 16 + (size_t)q * 4;
    *(uint32_t*)(g_wt + addr) = *reinterpret_cast<uint32_t*>(&h);
}

// ============================================================
// Main kernel
// ============================================================
__global__ __launch_bounds__(THREADS, 2)
void mlp_kernel(const float* __restrict__ pts,
                const float* __restrict__ b0, const float* __restrict__ b1,
                const float* __restrict__ b2, const float* __restrict__ b3,
                const float* __restrict__ b4, const float* __restrict__ b5,
                const float* __restrict__ b6, const float* __restrict__ b7,
                const float* __restrict__ wsdf, const float* __restrict__ bsdf,
                float* __restrict__ out) {
    extern __shared__ unsigned char smem[];
    const uint32_t sb = smem_u32(smem);
    const int tid = threadIdx.x;
    const int lane = tid & 31;
    const int warp = tid >> 5;
    const int warpM = warp >> 2;   // 0..1 (32 rows each)
    const int warpN = warp & 3;    // 0..3 (64 cols each)
    const int base = blockIdx.x * TILE_M;

    // B stream pointer (chunk 0) + first prefetch, overlaps prologue.
    const unsigned char* bp = g_wt + (size_t)(warpN * 4) * 512 + (size_t)lane * 16;
    uint4 bC = ldg128(bp);

    // ---- biases + head weights to smem ----
    {
        float* biasS = (float*)(smem + OFF_BIAS);
        biasS[tid]            = __ldg(b0 + tid);
        biasS[tid + 256]      = __ldg(b1 + tid);
        biasS[tid + 512]      = __ldg(b2 + tid);
        biasS[tid + 768]      = __ldg(b3 + tid);
        biasS[tid + 1024]     = __ldg(b4 + tid);
        biasS[tid + 1280]     = __ldg(b5 + tid);
        biasS[tid + 1536]     = __ldg(b6 + tid);
        biasS[tid + 1792]     = __ldg(b7 + tid);
        ((float*)(smem + OFF_WSDF))[tid] = __ldg(wsdf + tid);
    }

    // ---- harmonic embedding, parallel over (point, coord) ----
    {
        const int c = tid >> 6;
        const int p = tid & 63;
        const uint32_t ro = (uint32_t)p * 96u;
        if (c < 3) {
            float co = __ldg(pts + (size_t)(base + p) * 3 + c);
            float s[6], cs[6];
            float f = 1.0f;
            #pragma unroll
            for (int h = 0; h < 6; ++h) {
                sincosf(co * f, &s[h], &cs[h]);
                f *= 2.0f;
            }
            #pragma unroll
            for (int w = 0; w < 3; ++w) {
                uint32_t wh, wl;
                packsplit16(s[2 * w], s[2 * w + 1], wh, wl);
                *(uint32_t*)(smem + OFF_EMBH + ro + (c * 3 + w) * 4) = wh;
                *(uint32_t*)(smem + OFF_EMBL + ro + (c * 3 + w) * 4) = wl;
                packsplit16(cs[2 * w], cs[2 * w + 1], wh, wl);
                *(uint32_t*)(smem + OFF_EMBH + ro + (9 + c * 3 + w) * 4) = wh;
                *(uint32_t*)(smem + OFF_EMBL + ro + (9 + c * 3 + w) * 4) = wl;
            }
        } else {
            const float* pp = pts + (size_t)(base + p) * 3;
            float x = __ldg(pp), y = __ldg(pp + 1), z = __ldg(pp + 2);
            uint32_t wh, wl;
            packsplit16(x, y, wh, wl);
            *(uint32_t*)(smem + OFF_EMBH + ro + 18 * 4) = wh;
            *(uint32_t*)(smem + OFF_EMBL + ro + 18 * 4) = wl;
            packsplit16(z, 0.0f, wh, wl);
            *(uint32_t*)(smem + OFF_EMBH + ro + 19 * 4) = wh;
            *(uint32_t*)(smem + OFF_EMBL + ro + 19 * 4) = wl;
            #pragma unroll
            for (int w = 20; w < 24; ++w) {
                *(uint32_t*)(smem + OFF_EMBH + ro + w * 4) = 0u;
                *(uint32_t*)(smem + OFF_EMBL + ro + w * 4) = 0u;
            }
        }
    }
    __syncthreads();   // emb + biases + wsdf visible to all

    float acc[2][8][4];
    const int NCH[9] = {3, 16, 16, 16, 3, 16, 16, 16, 16};
    const int BIDX[9] = {0, 1, 2, 3, 0, 4, 5, 6, 7};

    #pragma unroll 1
    for (int ps = 0; ps < 9; ++ps) {
        const bool isEmb = (ps == 0 || ps == 4);
        if (ps != 5) {
            #pragma unroll
            for (int mt = 0; mt < 2; ++mt)
                #pragma unroll
                for (int nt = 0; nt < 8; ++nt)
                    #pragma unroll
                    for (int q = 0; q < 4; ++q) acc[mt][nt][q] = 0.0f;
        }
        const int nch = NCH[ps];

        // per-pass hoisted A-frag addressing:
        //   addr(chunk, mt, hi/lo) = rbH + (k2 ^ swzp) [+ mtoff] [+ lodel]
        // with k2 += 32 per chunk (all other terms constant).
        const uint32_t pitch = isEmb ? 96u : 512u;
        const uint32_t row   = (uint32_t)(warpM * 32 + (lane & 15));
        const uint32_t rbH   = sb + (isEmb ? OFF_EMBH : OFF_XH) + row * pitch;
        const uint32_t mtoff = 16u * pitch;
        const uint32_t lodel = isEmb ? (OFF_EMBL - OFF_EMBH) : (OFF_XL - OFF_XH);
        const uint32_t swzp  = isEmb ? 0u : (((uint32_t)lane & 7u) << 4);
        uint32_t k2 = (uint32_t)(lane >> 4) * 16u;

        #pragma unroll 1
        for (int c = 0; c < nch; ++c) {
            // A fragments (X or emb), 2 m-tiles, hi+lo
            uint32_t ah[2][4], al[2][4];
            {
                const uint32_t a0 = rbH + (k2 ^ swzp);
                ldsm4(ah[0], a0);
                ldsm4(ah[1], a0 + mtoff);
                ldsm4(al[0], a0 + lodel);
                ldsm4(al[1], a0 + lodel + mtoff);
                k2 += 32u;
            }

            #pragma unroll
            for (int jj = 0; jj < 4; ++jj) {
                // prefetch next (chunk, jj) B fragment; branchless [bp+imm]
                const unsigned char* np = (jj < 3) ? (bp + (jj + 1) * 512)
                                                   : (bp + CHUNK_BYTES);
                uint4 bN = ldg128(np);

                #pragma unroll
                for (int mt = 0; mt < 2; ++mt) {
                    mma16816(acc[mt][jj * 2],     ah[mt], bC.x, bC.y);
                    mma16816(acc[mt][jj * 2],     al[mt], bC.x, bC.y);
                    mma16816(acc[mt][jj * 2 + 1], ah[mt], bC.z, bC.w);
                    mma16816(acc[mt][jj * 2 + 1], al[mt], bC.z, bC.w);
                }
                bC = bN;
            }
            bp += CHUNK_BYTES;
        }

        // ---- epilogue ----
        if (ps == 4) continue;  // skip-concat: keep accumulating
        const float* bS = (const float*)(smem + OFF_BIAS) + BIDX[ps] * 256;
        if (ps < 8) {
            // X rows [warpM*32, +32) touched only by this 4-warp half.
            half_bar(1 + warpM);   // half's reads of X/emb rows done
            #pragma unroll
            for (int mt = 0; mt < 2; ++mt) {
                const int r0 = warpM * 32 + mt * 16 + (lane >> 2);
                const int r1 = r0 + 8;
                #pragma unroll
                for (int nt = 0; nt < 8; ++nt) {
                    const int col = warpN * 64 + nt * 8 + (lane & 3) * 2;
                    const float bb0 = bS[col];
                    const float bb1 = bS[col + 1];
                    float v00 = fmaxf(acc[mt][nt][0] + bb0, 0.0f);
                    float v01 = fmaxf(acc[mt][nt][1] + bb1, 0.0f);
                    float v10 = fmaxf(acc[mt][nt][2] + bb0, 0.0f);
                    float v11 = fmaxf(acc[mt][nt][3] + bb1, 0.0f);
                    uint32_t wh, wl;
                    packsplit16(v00, v01, wh, wl);
                    uint32_t o0 = (uint32_t)r0 * 512u
                                  + (((uint32_t)col * 2u) ^ (((uint32_t)r0 & 7u) << 4));
                    *(uint32_t*)(smem + OFF_XH + o0) = wh;
                    *(uint32_t*)(smem + OFF_XL + o0) = wl;
                    packsplit16(v10, v11, wh, wl);
                    uint32_t o1 = (uint32_t)r1 * 512u
                                  + (((uint32_t)col * 2u) ^ (((uint32_t)r1 & 7u) << 4));
                    *(uint32_t*)(smem + OFF_XH + o1) = wh;
                    *(uint32_t*)(smem + OFF_XL + o1) = wl;
                }
            }
            half_bar(1 + warpM);   // writes visible to half before next pass
        } else {
            // SDF head: relu(D + b7) . wsdf + bsdf
            const float* wS = (const float*)(smem + OFF_WSDF);
            float rp[4] = {0.0f, 0.0f, 0.0f, 0.0f};
            #pragma unroll
            for (int mt = 0; mt < 2; ++mt)
                #pragma unroll
                for (int nt = 0; nt < 8; ++nt) {
                    const int col = warpN * 64 + nt * 8 + (lane & 3) * 2;
                    const float bb0 = bS[col];
                    const float bb1 = bS[col + 1];
                    const float w0v = wS[col], w1v = wS[col + 1];
                    rp[mt * 2]     += fmaxf(acc[mt][nt][0] + bb0, 0.0f) * w0v
                                    + fmaxf(acc[mt][nt][1] + bb1, 0.0f) * w1v;
                    rp[mt * 2 + 1] += fmaxf(acc[mt][nt][2] + bb0, 0.0f) * w0v
                                    + fmaxf(acc[mt][nt][3] + bb1, 0.0f) * w1v;
                }
            #pragma unroll
            for (int i = 0; i < 4; ++i) {
                rp[i] += __shfl_xor_sync(0xffffffffu, rp[i], 1);
                rp[i] += __shfl_xor_sync(0xffffffffu, rp[i], 2);
            }
            float* red = (float*)(smem + OFF_RED);
            __syncthreads();   // ALL warps past emb reads; reuse region
            if ((lane & 3) == 0) {
                #pragma unroll
                for (int mt = 0; mt < 2; ++mt) {
                    int row2 = warpM * 32 + mt * 16 + (lane >> 2);
                    red[row2 * 4 + warpN] = rp[mt * 2];
                    red[(row2 + 8) * 4 + warpN] = rp[mt * 2 + 1];
                }
            }
            __syncthreads();
            if (tid < TILE_M) {
                out[base + tid] = red[tid * 4] + red[tid * 4 + 1]
                                + red[tid * 4 + 2] + red[tid * 4 + 3] + __ldg(bsdf);
            }
        }
    }
}

// ============================================================
extern "C" void kernel_launch(void* const* d_in, const int* in_sizes, int n_in,
                              void* d_out, int out_size) {
    const float* pts = (const float*)d_in[0];
    const float* W[8];
    const float* B[8];
    for (int i = 0; i < 8; ++i) {
        W[i] = (const float*)d_in[1 + 2 * i];
        B[i] = (const float*)d_in[2 + 2 * i];
    }
    const float* wsdf = (const float*)d_in[17];
    const float* bsdf = (const float*)d_in[18];
    int n = in_sizes[0] / 3;     // 262144
    int grid = n / TILE_M;       // 4096

    prep_kernel<<<944, 256>>>(W[0], W[1], W[2], W[3], W[4], W[5], W[6], W[7]);

    cudaFuncSetAttribute(mlp_kernel,
                         cudaFuncAttributeMaxDynamicSharedMemorySize, SMEM_BYTES);
    mlp_kernel<<<grid, THREADS, SMEM_BYTES>>>(
        pts, B[0], B[1], B[2], B[3], B[4], B[5], B[6], B[7],
        wsdf, bsdf, (float*)d_out);
}